// round 1
// baseline (speedup 1.0000x reference)
#include <cuda_runtime.h>
#include <math.h>

#define NMAX 4096
#define DH   256
#define DCAT 896

// ---------------- scratch (device globals; no runtime alloc) ----------------
__device__ __align__(16) float g_Xcat[2][(size_t)NMAX * DCAT];   // concat features per graph
__device__ __align__(16) float g_tmp1[(size_t)NMAX * DH];
__device__ __align__(16) float g_tmp2[(size_t)NMAX * DH];
__device__ __align__(16) float g_agg1[(size_t)NMAX * DH];
__device__ __align__(16) float g_agg2[(size_t)NMAX * DH];
__device__ __align__(16) float g_H[2][(size_t)NMAX * DH];
__device__ __align__(16) float g_E[(size_t)NMAX * NMAX];         // exp(20*(match+eps)), 64MB
__device__ __align__(16) float g_r[NMAX];
__device__ __align__(16) float g_c[NMAX];
__device__ __align__(16) float g_colsum[NMAX];
__device__ __align__(16) int   g_cnt_a[NMAX];
__device__ __align__(16) int   g_cnt_b[NMAX];
__device__ __align__(16) float g_inv_a[NMAX];
__device__ __align__(16) float g_inv_b[NMAX];

// ---------------- small utility kernels ----------------
__global__ void fill_f(float* p, float v, int n) {
    int t = blockIdx.x * blockDim.x + threadIdx.x;
    if (t < n) p[t] = v;
}
__global__ void fill_i(int* p, int v, int n) {
    int t = blockIdx.x * blockDim.x + threadIdx.x;
    if (t < n) p[t] = v;
}
__global__ void count_k(const int* __restrict__ idx, int* __restrict__ cnt, int E) {
    int t = blockIdx.x * blockDim.x + threadIdx.x;
    if (t < E) atomicAdd(&cnt[idx[t]], 1);
}
__global__ void inv_k(const int* __restrict__ cnt, float* __restrict__ inv, int n) {
    int t = blockIdx.x * blockDim.x + threadIdx.x;
    if (t < n) inv[t] = 1.0f / (float)max(cnt[t], 1);
}
__global__ void copy_x(const float* __restrict__ x, float* __restrict__ Xc, int N) {
    int t = blockIdx.x * blockDim.x + threadIdx.x;
    int row = t >> 5;           // 32 float4 per 128-dim row
    int c = (t & 31) << 2;
    if (row < N)
        *reinterpret_cast<float4*>(Xc + (size_t)row * DCAT + c) =
            *reinterpret_cast<const float4*>(x + (size_t)row * 128 + c);
}
__global__ void recip_k(const float* __restrict__ a, float* __restrict__ b, int n) {
    int t = blockIdx.x * blockDim.x + threadIdx.x;
    if (t < n) b[t] = 1.0f / a[t];
}

// ---------------- SGEMM: 64x64x16 tile, 256 thr, 4x4/thread ----------------
// BT=0: C = A(MxK) * B(KxN)            (B row-major KxN)
// BT=1: C = A(MxK) * B(NxK)^T          (B row-major NxK; dot-product form)
// EPI: 0 plain, 1 relu(acc+bias[col]+add1[row,col]+add2[row,col]),
//      2 expf(20*(acc+1e-10)), 3 acc+bias[col]
template <int BT, int EPI>
__global__ void __launch_bounds__(256) sgemm(
    const float* __restrict__ A, int lda,
    const float* __restrict__ B, int ldb,
    float* __restrict__ C, int ldc,
    int M, int N, int K,
    const float* __restrict__ bias,
    const float* __restrict__ add1,
    const float* __restrict__ add2)
{
    __shared__ float As[16][64];
    __shared__ float Bs[16][64];
    const int tid = threadIdx.x;
    const int tx = tid & 15, ty = tid >> 4;
    const int row0 = blockIdx.y * 64, col0 = blockIdx.x * 64;
    const int lr = tid >> 2;          // 0..63 tile row
    const int lk = (tid & 3) << 2;    // 0,4,8,12 k-subchunk

    float acc[4][4] = {};

    for (int k0 = 0; k0 < K; k0 += 16) {
        float4 av = make_float4(0.f, 0.f, 0.f, 0.f);
        int arow = row0 + lr;
        if (arow < M)
            av = *reinterpret_cast<const float4*>(A + (size_t)arow * lda + k0 + lk);
        As[lk + 0][lr] = av.x; As[lk + 1][lr] = av.y;
        As[lk + 2][lr] = av.z; As[lk + 3][lr] = av.w;

        if (BT == 0) {
            int bk = tid >> 4;          // 0..15
            int bc = (tid & 15) << 2;   // 0..60
            *reinterpret_cast<float4*>(&Bs[bk][bc]) =
                *reinterpret_cast<const float4*>(B + (size_t)(k0 + bk) * ldb + col0 + bc);
        } else {
            float4 bv = *reinterpret_cast<const float4*>(B + (size_t)(col0 + lr) * ldb + k0 + lk);
            Bs[lk + 0][lr] = bv.x; Bs[lk + 1][lr] = bv.y;
            Bs[lk + 2][lr] = bv.z; Bs[lk + 3][lr] = bv.w;
        }
        __syncthreads();

        #pragma unroll
        for (int kk = 0; kk < 16; kk++) {
            float a[4], b[4];
            *reinterpret_cast<float4*>(a) = *reinterpret_cast<const float4*>(&As[kk][ty << 2]);
            *reinterpret_cast<float4*>(b) = *reinterpret_cast<const float4*>(&Bs[kk][tx << 2]);
            #pragma unroll
            for (int i = 0; i < 4; i++)
                #pragma unroll
                for (int j = 0; j < 4; j++)
                    acc[i][j] = fmaf(a[i], b[j], acc[i][j]);
        }
        __syncthreads();
    }

    #pragma unroll
    for (int i = 0; i < 4; i++) {
        int row = row0 + (ty << 2) + i;
        if (row >= M) continue;
        #pragma unroll
        for (int j = 0; j < 4; j++) {
            int col = col0 + (tx << 2) + j;
            float v = acc[i][j];
            if (EPI == 1)
                v = fmaxf(v + bias[col] + add1[(size_t)row * DH + col]
                            + add2[(size_t)row * DH + col], 0.f);
            else if (EPI == 2)
                v = expf(20.f * (v + 1e-10f));
            else if (EPI == 3)
                v = v + bias[col];
            C[(size_t)row * ldc + col] = v;
        }
    }
}

// ---------------- scatter-mean (sum with pre-scaled 1/count) ----------------
__global__ void scatter_k(const float* __restrict__ vals,
                          const int* __restrict__ gidx,
                          const int* __restrict__ sidx,
                          const float* __restrict__ invc,
                          float* __restrict__ out, int E)
{
    int t = blockIdx.x * blockDim.x + threadIdx.x;
    int e = t >> 6;            // 64 float4 per 256-dim row
    int d = (t & 63) << 2;
    if (e >= E) return;
    int g = gidx[e], s = sidx[e];
    float sc = invc[s];
    float4 v = *reinterpret_cast<const float4*>(vals + (size_t)g * DH + d);
    float* o = out + (size_t)s * DH + d;
    atomicAdd(o + 0, v.x * sc);
    atomicAdd(o + 1, v.y * sc);
    atomicAdd(o + 2, v.z * sc);
    atomicAdd(o + 3, v.w * sc);
}

// ---------------- row L2 normalize (in place) ----------------
__global__ void l2norm_k(float* __restrict__ H) {
    int row = blockIdx.x;
    int tid = threadIdx.x;  // 256
    float v = H[(size_t)row * DH + tid];
    __shared__ float red[256];
    red[tid] = v * v;
    __syncthreads();
    for (int s = 128; s > 0; s >>= 1) {
        if (tid < s) red[tid] += red[tid + s];
        __syncthreads();
    }
    float sc = 1.0f / fmaxf(sqrtf(red[0]), 1e-12f);
    H[(size_t)row * DH + tid] = v * sc;
}

// ---------------- sinkhorn factor passes ----------------
// colsum[j] += sum_{i in stripe} E[i][j]*r[i]   grid(16, 32), 256 thr
__global__ void colsum_k(const float* __restrict__ Eb, const float* __restrict__ r,
                         float* __restrict__ cs)
{
    int j = blockIdx.x * 256 + threadIdx.x;
    int i0 = blockIdx.y * 128;
    float acc = 0.f;
    #pragma unroll 4
    for (int i = 0; i < 128; i++)
        acc += Eb[(size_t)(i0 + i) * NMAX + j] * __ldg(&r[i0 + i]);
    atomicAdd(&cs[j], acc);
}

// r[i] = 1 / sum_j E[i][j]*c[j]   (one block per row)
__global__ void rowsum_k(const float* __restrict__ Eb, const float* __restrict__ c,
                         float* __restrict__ r)
{
    int i = blockIdx.x, tid = threadIdx.x;   // 256 threads
    const float4* row = reinterpret_cast<const float4*>(Eb + (size_t)i * NMAX);
    const float4* c4 = reinterpret_cast<const float4*>(c);
    float acc = 0.f;
    for (int j = tid; j < NMAX / 4; j += 256) {
        float4 e = row[j], cv = c4[j];
        acc += e.x * cv.x + e.y * cv.y + e.z * cv.z + e.w * cv.w;
    }
    __shared__ float red[256];
    red[tid] = acc;
    __syncthreads();
    for (int s = 128; s > 0; s >>= 1) {
        if (tid < s) red[tid] += red[tid + s];
        __syncthreads();
    }
    if (tid == 0) r[i] = 1.0f / red[0];
}

// out[i][j] = E[i][j]*r[i]*c[j]   for i < 4000
__global__ void finalize_k(const float* __restrict__ Eb, const float* __restrict__ r,
                           const float* __restrict__ c, float* __restrict__ out, int rows)
{
    int t = blockIdx.x * blockDim.x + threadIdx.x;   // rows * 1024 float4 slots
    if (t >= rows * (NMAX / 4)) return;
    int i = t >> 10, j = t & 1023;
    float ri = r[i];
    float4 e = reinterpret_cast<const float4*>(Eb)[(size_t)i * (NMAX / 4) + j];
    float4 cv = reinterpret_cast<const float4*>(c)[j];
    float4 o;
    o.x = e.x * ri * cv.x; o.y = e.y * ri * cv.y;
    o.z = e.z * ri * cv.z; o.w = e.w * ri * cv.w;
    reinterpret_cast<float4*>(out)[t] = o;
}

// ---------------- host driver ----------------
static inline int cdiv(int a, int b) { return (a + b - 1) / b; }

extern "C" void kernel_launch(void* const* d_in, const int* in_sizes, int n_in,
                              void* d_out, int out_size)
{
    const float* x_s = (const float*)d_in[0];
    const float* x_t = (const float*)d_in[1];
    const int* edges = (const int*)d_in[2];
    const int* edget = (const int*)d_in[3];
    const float* W1[3], *W2[3], *Wr[3], *br[3];
    for (int l = 0; l < 3; l++) {
        W1[l] = (const float*)d_in[4 + 4 * l];
        W2[l] = (const float*)d_in[5 + 4 * l];
        Wr[l] = (const float*)d_in[6 + 4 * l];
        br[l] = (const float*)d_in[7 + 4 * l];
    }
    const float* final_w = (const float*)d_in[16];
    const float* final_b = (const float*)d_in[17];

    const int NS = in_sizes[0] / 128;      // 4000
    const int NT = in_sizes[1] / 128;      // 4096
    const int ES = in_sizes[2] / 2;
    const int ET = in_sizes[3] / 2;

    float *Xcat, *tmp1, *tmp2, *agg1, *agg2, *Hb, *Eb, *rr, *cc, *csum, *inv_a, *inv_b;
    int *cnt_a, *cnt_b;
    cudaGetSymbolAddress((void**)&Xcat, g_Xcat);
    cudaGetSymbolAddress((void**)&tmp1, g_tmp1);
    cudaGetSymbolAddress((void**)&tmp2, g_tmp2);
    cudaGetSymbolAddress((void**)&agg1, g_agg1);
    cudaGetSymbolAddress((void**)&agg2, g_agg2);
    cudaGetSymbolAddress((void**)&Hb, g_H);
    cudaGetSymbolAddress((void**)&Eb, g_E);
    cudaGetSymbolAddress((void**)&rr, g_r);
    cudaGetSymbolAddress((void**)&cc, g_c);
    cudaGetSymbolAddress((void**)&csum, g_colsum);
    cudaGetSymbolAddress((void**)&cnt_a, g_cnt_a);
    cudaGetSymbolAddress((void**)&cnt_b, g_cnt_b);
    cudaGetSymbolAddress((void**)&inv_a, g_inv_a);
    cudaGetSymbolAddress((void**)&inv_b, g_inv_b);

    for (int gi = 0; gi < 2; gi++) {
        const float* x = gi == 0 ? x_s : x_t;
        const int* ep = gi == 0 ? edges : edget;
        int N = gi == 0 ? NS : NT;
        int E = gi == 0 ? ES : ET;
        const int* src = ep;
        const int* dst = ep + E;
        float* Xc = Xcat + (size_t)gi * NMAX * DCAT;
        float* H = Hb + (size_t)gi * NMAX * DH;

        copy_x<<<cdiv(N * 32, 256), 256>>>(x, Xc, N);
        fill_i<<<cdiv(NMAX, 256), 256>>>(cnt_a, 0, NMAX);
        fill_i<<<cdiv(NMAX, 256), 256>>>(cnt_b, 0, NMAX);
        count_k<<<cdiv(E, 256), 256>>>(dst, cnt_a, E);   // in-degree (for out1)
        count_k<<<cdiv(E, 256), 256>>>(src, cnt_b, E);   // out-degree (for out2)
        inv_k<<<cdiv(NMAX, 256), 256>>>(cnt_a, inv_a, NMAX);
        inv_k<<<cdiv(NMAX, 256), 256>>>(cnt_b, inv_b, NMAX);

        int off = 0, fan = 128;
        for (int l = 0; l < 3; l++) {
            const float* hA = Xc + off;
            dim3 grid(4, cdiv(N, 64));
            sgemm<0, 0><<<grid, 256>>>(hA, DCAT, W1[l], DH, tmp1, DH, N, DH, fan,
                                       nullptr, nullptr, nullptr);
            sgemm<0, 0><<<grid, 256>>>(hA, DCAT, W2[l], DH, tmp2, DH, N, DH, fan,
                                       nullptr, nullptr, nullptr);
            fill_f<<<cdiv(N * DH, 256), 256>>>(agg1, 0.f, N * DH);
            fill_f<<<cdiv(N * DH, 256), 256>>>(agg2, 0.f, N * DH);
            scatter_k<<<cdiv(E * 64, 256), 256>>>(tmp1, src, dst, inv_a, agg1, E);
            scatter_k<<<cdiv(E * 64, 256), 256>>>(tmp2, dst, src, inv_b, agg2, E);
            int noff = off + fan;   // 0->128, 128->384, 384->640
            sgemm<0, 1><<<grid, 256>>>(hA, DCAT, Wr[l], DH, Xc + noff, DCAT, N, DH, fan,
                                       br[l], agg1, agg2);
            off = noff;
            fan = DH;
        }
        // final linear: H = Xcat @ final_w + final_b   (K = 896)
        dim3 gridf(4, cdiv(N, 64));
        sgemm<0, 3><<<gridf, 256>>>(Xc, DCAT, final_w, DH, H, DH, N, DH, DCAT,
                                    final_b, nullptr, nullptr);
        l2norm_k<<<N, 256>>>(H);
    }

    // match -> E = exp(20*(Hs_n @ Ht_n^T + 1e-10))
    {
        float* Hs = Hb;
        float* Ht = Hb + (size_t)NMAX * DH;
        dim3 gm(NMAX / 64, cdiv(NS, 64));
        sgemm<1, 2><<<gm, 256>>>(Hs, DH, Ht, DH, Eb, NMAX, NS, NMAX, DH,
                                 nullptr, nullptr, nullptr);
        // dummy rows: exp(20*(eps+eps)) == 1.0f in fp32
        fill_f<<<cdiv((NMAX - NS) * NMAX, 256), 256>>>(Eb + (size_t)NS * NMAX, 1.0f,
                                                       (NMAX - NS) * NMAX);
    }

    // sinkhorn via row/col scale factors: 5x (col-norm, row-norm)
    fill_f<<<cdiv(NMAX, 256), 256>>>(rr, 1.0f, NMAX);
    for (int it = 0; it < 5; it++) {
        fill_f<<<cdiv(NMAX, 256), 256>>>(csum, 0.f, NMAX);
        colsum_k<<<dim3(NMAX / 256, 32), 256>>>(Eb, rr, csum);
        recip_k<<<cdiv(NMAX, 256), 256>>>(csum, cc, NMAX);
        rowsum_k<<<NMAX, 256>>>(Eb, cc, rr);
    }
    finalize_k<<<cdiv(NS * (NMAX / 4), 256), 256>>>(Eb, rr, cc, (float*)d_out, NS);
}

// round 3
// speedup vs baseline: 1.0882x; 1.0882x over previous
#include <cuda_runtime.h>
#include <cuda_bf16.h>
#include <math.h>
#include <stdint.h>

#define NMAX 4096
#define DH   256
#define DCAT 896

// ---------------- scratch (device globals; no runtime alloc) ----------------
__device__ __align__(16) float g_Xcat[2][(size_t)NMAX * DCAT];   // concat features per graph
__device__ __align__(16) float g_tmp1[(size_t)NMAX * DH];
__device__ __align__(16) float g_tmp2[(size_t)NMAX * DH];
__device__ __align__(16) float g_agg1[(size_t)NMAX * DH];
__device__ __align__(16) float g_agg2[(size_t)NMAX * DH];
__device__ __align__(16) float g_H[2][(size_t)NMAX * DH];
__device__ __align__(16) float g_E[(size_t)NMAX * NMAX];         // exp(20*(match+eps)), 64MB
__device__ __align__(16) float g_r[NMAX];
__device__ __align__(16) float g_c[NMAX];
__device__ __align__(16) float g_colsum[NMAX];
__device__ __align__(16) int   g_cnt_a[NMAX];
__device__ __align__(16) int   g_cnt_b[NMAX];
__device__ __align__(16) float g_inv_a[NMAX];
__device__ __align__(16) float g_inv_b[NMAX];
// bf16 split copies of H for tensor-core match GEMM
__device__ __align__(16) __nv_bfloat16 g_sh[2][(size_t)NMAX * DH];
__device__ __align__(16) __nv_bfloat16 g_sl[2][(size_t)NMAX * DH];

// ---------------- small utility kernels ----------------
__global__ void fill_f(float* p, float v, int n) {
    int t = blockIdx.x * blockDim.x + threadIdx.x;
    if (t < n) p[t] = v;
}
__global__ void fill_i(int* p, int v, int n) {
    int t = blockIdx.x * blockDim.x + threadIdx.x;
    if (t < n) p[t] = v;
}
__global__ void count_k(const int* __restrict__ idx, int* __restrict__ cnt, int E) {
    int t = blockIdx.x * blockDim.x + threadIdx.x;
    if (t < E) atomicAdd(&cnt[idx[t]], 1);
}
__global__ void inv_k(const int* __restrict__ cnt, float* __restrict__ inv, int n) {
    int t = blockIdx.x * blockDim.x + threadIdx.x;
    if (t < n) inv[t] = 1.0f / (float)max(cnt[t], 1);
}
__global__ void copy_x(const float* __restrict__ x, float* __restrict__ Xc, int N) {
    int t = blockIdx.x * blockDim.x + threadIdx.x;
    int row = t >> 5;
    int c = (t & 31) << 2;
    if (row < N)
        *reinterpret_cast<float4*>(Xc + (size_t)row * DCAT + c) =
            *reinterpret_cast<const float4*>(x + (size_t)row * 128 + c);
}
__global__ void recip_k(const float* __restrict__ a, float* __restrict__ b, int n) {
    int t = blockIdx.x * blockDim.x + threadIdx.x;
    if (t < n) b[t] = 1.0f / a[t];
}
// split fp32 into bf16 hi + lo residual
__global__ void split_k(const float* __restrict__ H, __nv_bfloat16* __restrict__ hi,
                        __nv_bfloat16* __restrict__ lo, int n)
{
    int t = blockIdx.x * blockDim.x + threadIdx.x;
    if (t >= n) return;
    float v = H[t];
    __nv_bfloat16 h = __float2bfloat16(v);
    float r = v - __bfloat162float(h);
    hi[t] = h;
    lo[t] = __float2bfloat16(r);
}

// ---------------- SGEMM (FFMA path for GNN) ----------------
template <int BT, int EPI>
__global__ void __launch_bounds__(256) sgemm(
    const float* __restrict__ A, int lda,
    const float* __restrict__ B, int ldb,
    float* __restrict__ C, int ldc,
    int M, int N, int K,
    const float* __restrict__ bias,
    const float* __restrict__ add1,
    const float* __restrict__ add2)
{
    __shared__ float As[16][64];
    __shared__ float Bs[16][64];
    const int tid = threadIdx.x;
    const int tx = tid & 15, ty = tid >> 4;
    const int row0 = blockIdx.y * 64, col0 = blockIdx.x * 64;
    const int lr = tid >> 2;
    const int lk = (tid & 3) << 2;

    float acc[4][4] = {};

    for (int k0 = 0; k0 < K; k0 += 16) {
        float4 av = make_float4(0.f, 0.f, 0.f, 0.f);
        int arow = row0 + lr;
        if (arow < M)
            av = *reinterpret_cast<const float4*>(A + (size_t)arow * lda + k0 + lk);
        As[lk + 0][lr] = av.x; As[lk + 1][lr] = av.y;
        As[lk + 2][lr] = av.z; As[lk + 3][lr] = av.w;

        if (BT == 0) {
            int bk = tid >> 4;
            int bc = (tid & 15) << 2;
            *reinterpret_cast<float4*>(&Bs[bk][bc]) =
                *reinterpret_cast<const float4*>(B + (size_t)(k0 + bk) * ldb + col0 + bc);
        } else {
            float4 bv = *reinterpret_cast<const float4*>(B + (size_t)(col0 + lr) * ldb + k0 + lk);
            Bs[lk + 0][lr] = bv.x; Bs[lk + 1][lr] = bv.y;
            Bs[lk + 2][lr] = bv.z; Bs[lk + 3][lr] = bv.w;
        }
        __syncthreads();

        #pragma unroll
        for (int kk = 0; kk < 16; kk++) {
            float a[4], b[4];
            *reinterpret_cast<float4*>(a) = *reinterpret_cast<const float4*>(&As[kk][ty << 2]);
            *reinterpret_cast<float4*>(b) = *reinterpret_cast<const float4*>(&Bs[kk][tx << 2]);
            #pragma unroll
            for (int i = 0; i < 4; i++)
                #pragma unroll
                for (int j = 0; j < 4; j++)
                    acc[i][j] = fmaf(a[i], b[j], acc[i][j]);
        }
        __syncthreads();
    }

    #pragma unroll
    for (int i = 0; i < 4; i++) {
        int row = row0 + (ty << 2) + i;
        if (row >= M) continue;
        #pragma unroll
        for (int j = 0; j < 4; j++) {
            int col = col0 + (tx << 2) + j;
            float v = acc[i][j];
            if (EPI == 1)
                v = fmaxf(v + bias[col] + add1[(size_t)row * DH + col]
                            + add2[(size_t)row * DH + col], 0.f);
            else if (EPI == 3)
                v = v + bias[col];
            C[(size_t)row * ldc + col] = v;
        }
    }
}

// ---------------- mma.sync bf16 helpers (baseline PTX, no arch-'a' features) --
__device__ __forceinline__ uint32_t smem_u32(const void* p) {
    uint32_t a;
    asm("{ .reg .u64 t; cvta.to.shared.u64 t, %1; cvt.u32.u64 %0, t; }" : "=r"(a) : "l"(p));
    return a;
}
__device__ __forceinline__ void ldm_x4(uint32_t* r, uint32_t addr) {
    asm volatile("ldmatrix.sync.aligned.m8n8.x4.shared.b16 {%0,%1,%2,%3}, [%4];"
        : "=r"(r[0]), "=r"(r[1]), "=r"(r[2]), "=r"(r[3]) : "r"(addr));
}
__device__ __forceinline__ void mma_bf16(float* d, const uint32_t* a, uint32_t b0, uint32_t b1) {
    asm volatile(
        "mma.sync.aligned.m16n8k16.row.col.f32.bf16.bf16.f32 "
        "{%0,%1,%2,%3}, {%4,%5,%6,%7}, {%8,%9}, {%0,%1,%2,%3};"
        : "+f"(d[0]), "+f"(d[1]), "+f"(d[2]), "+f"(d[3])
        : "r"(a[0]), "r"(a[1]), "r"(a[2]), "r"(a[3]), "r"(b0), "r"(b1));
}

// ---------------- tensor-core match GEMM (split-2 bf16) ----------------
// E[row][col] = exp(20*(dot(Hs_n[row], Ht_n[col]) + 1e-10))
// 3 passes: Ah*Bh, Ah*Bl, Al*Bh, fp32 accumulate.
// CTA tile 128x128, 8 warps (4m x 2n), warp tile 32x64 = 2x8 m16n8k16.
#define SPAD 40   // smem row stride in bf16 elems (80B: conflict-free for ldmatrix)

__global__ void __launch_bounds__(256, 2) match_mma_kernel(
    const __nv_bfloat16* __restrict__ Ah, const __nv_bfloat16* __restrict__ Al,
    const __nv_bfloat16* __restrict__ Bh, const __nv_bfloat16* __restrict__ Bl,
    float* __restrict__ Eout)
{
    __shared__ __nv_bfloat16 sA[128 * SPAD];
    __shared__ __nv_bfloat16 sB[128 * SPAD];
    const int tid = threadIdx.x;
    const int wid = tid >> 5, lane = tid & 31;
    const int wm = wid & 3, wn = wid >> 2;           // 4 x 2 warp grid
    const int row0 = blockIdx.y * 128, col0 = blockIdx.x * 128;

    float acc[2][8][4];
    #pragma unroll
    for (int i = 0; i < 2; i++)
        #pragma unroll
        for (int j = 0; j < 8; j++)
            #pragma unroll
            for (int q = 0; q < 4; q++) acc[i][j][q] = 0.f;

    // precomputed smem addresses
    const int a_r = wm * 32 + (lane & 15);           // lanes16-31 same rows as 0-15? no:
    // A ldmatrix addressing: lanes 0-15 -> row base+lane, col +0; lanes 16-31 -> row base+lane-16, col +8
    const int a_row = wm * 32 + (lane < 16 ? lane : lane - 16);
    const int a_col = (lane < 16 ? 0 : 8);
    (void)a_r;
    const int b_row = wn * 64 + (lane & 7);
    const int b_col = (lane >> 3) * 8;               // 0,8,16,24

    #pragma unroll
    for (int p = 0; p < 3; p++) {
        const __nv_bfloat16* Ag = (p == 2 ? Al : Ah) + (size_t)row0 * DH;
        const __nv_bfloat16* Bg = (p == 1 ? Bl : Bh) + (size_t)col0 * DH;
        for (int kc = 0; kc < DH / 32; kc++) {
            __syncthreads();
            // load 128x32 bf16 tiles (512 uint4 each; 2 per thread per tile)
            #pragma unroll
            for (int r = 0; r < 2; r++) {
                int idx = tid * 2 + r;               // 0..511
                int row = idx >> 2, q = idx & 3;
                *reinterpret_cast<uint4*>(sA + row * SPAD + q * 8) =
                    *reinterpret_cast<const uint4*>(Ag + (size_t)row * DH + kc * 32 + q * 8);
                *reinterpret_cast<uint4*>(sB + row * SPAD + q * 8) =
                    *reinterpret_cast<const uint4*>(Bg + (size_t)row * DH + kc * 32 + q * 8);
            }
            __syncthreads();

            // B fragments: per ntile j, x4 covers k0-31 (4 8x8 matrices)
            uint32_t bfr[8][4];
            #pragma unroll
            for (int j = 0; j < 8; j++)
                ldm_x4(bfr[j], smem_u32(sB + (b_row + j * 8) * SPAD + b_col));

            #pragma unroll
            for (int h = 0; h < 2; h++) {            // two k16 halves
                #pragma unroll
                for (int i = 0; i < 2; i++) {        // two m16 tiles
                    uint32_t afr[4];
                    ldm_x4(afr, smem_u32(sA + (a_row + i * 16) * SPAD + h * 16 + a_col));
                    #pragma unroll
                    for (int j = 0; j < 8; j++)
                        mma_bf16(acc[i][j], afr, bfr[j][2 * h], bfr[j][2 * h + 1]);
                }
            }
        }
    }

    // epilogue: exp(20*(v + 1e-10))
    const int er = lane >> 2, ec = (lane & 3) * 2;
    #pragma unroll
    for (int i = 0; i < 2; i++) {
        int gr0 = row0 + wm * 32 + i * 16 + er;
        #pragma unroll
        for (int j = 0; j < 8; j++) {
            int gc = col0 + wn * 64 + j * 8 + ec;
            float2 o0, o1;
            o0.x = expf(20.f * (acc[i][j][0] + 1e-10f));
            o0.y = expf(20.f * (acc[i][j][1] + 1e-10f));
            o1.x = expf(20.f * (acc[i][j][2] + 1e-10f));
            o1.y = expf(20.f * (acc[i][j][3] + 1e-10f));
            *reinterpret_cast<float2*>(Eout + (size_t)gr0 * NMAX + gc) = o0;
            *reinterpret_cast<float2*>(Eout + (size_t)(gr0 + 8) * NMAX + gc) = o1;
        }
    }
}

// ---------------- scatter-mean (sum with pre-scaled 1/count) ----------------
__global__ void scatter_k(const float* __restrict__ vals,
                          const int* __restrict__ gidx,
                          const int* __restrict__ sidx,
                          const float* __restrict__ invc,
                          float* __restrict__ out, int E)
{
    int t = blockIdx.x * blockDim.x + threadIdx.x;
    int e = t >> 6;
    int d = (t & 63) << 2;
    if (e >= E) return;
    int g = gidx[e], s = sidx[e];
    float sc = invc[s];
    float4 v = *reinterpret_cast<const float4*>(vals + (size_t)g * DH + d);
    float* o = out + (size_t)s * DH + d;
    atomicAdd(o + 0, v.x * sc);
    atomicAdd(o + 1, v.y * sc);
    atomicAdd(o + 2, v.z * sc);
    atomicAdd(o + 3, v.w * sc);
}

// ---------------- row L2 normalize (in place) ----------------
__global__ void l2norm_k(float* __restrict__ H) {
    int row = blockIdx.x;
    int tid = threadIdx.x;
    float v = H[(size_t)row * DH + tid];
    __shared__ float red[256];
    red[tid] = v * v;
    __syncthreads();
    for (int s = 128; s > 0; s >>= 1) {
        if (tid < s) red[tid] += red[tid + s];
        __syncthreads();
    }
    float sc = 1.0f / fmaxf(sqrtf(red[0]), 1e-12f);
    H[(size_t)row * DH + tid] = v * sc;
}

// ---------------- sinkhorn factor passes ----------------
__global__ void colsum_k(const float* __restrict__ Eb, const float* __restrict__ r,
                         float* __restrict__ cs)
{
    int j = blockIdx.x * 256 + threadIdx.x;
    int i0 = blockIdx.y * 128;
    float acc = 0.f;
    #pragma unroll 4
    for (int i = 0; i < 128; i++)
        acc += Eb[(size_t)(i0 + i) * NMAX + j] * __ldg(&r[i0 + i]);
    atomicAdd(&cs[j], acc);
}

__global__ void rowsum_k(const float* __restrict__ Eb, const float* __restrict__ c,
                         float* __restrict__ r)
{
    int i = blockIdx.x, tid = threadIdx.x;
    const float4* row = reinterpret_cast<const float4*>(Eb + (size_t)i * NMAX);
    const float4* c4 = reinterpret_cast<const float4*>(c);
    float acc = 0.f;
    for (int j = tid; j < NMAX / 4; j += 256) {
        float4 e = row[j], cv = c4[j];
        acc += e.x * cv.x + e.y * cv.y + e.z * cv.z + e.w * cv.w;
    }
    __shared__ float red[256];
    red[tid] = acc;
    __syncthreads();
    for (int s = 128; s > 0; s >>= 1) {
        if (tid < s) red[tid] += red[tid + s];
        __syncthreads();
    }
    if (tid == 0) r[i] = 1.0f / red[0];
}

__global__ void finalize_k(const float* __restrict__ Eb, const float* __restrict__ r,
                           const float* __restrict__ c, float* __restrict__ out, int rows)
{
    int t = blockIdx.x * blockDim.x + threadIdx.x;
    if (t >= rows * (NMAX / 4)) return;
    int i = t >> 10, j = t & 1023;
    float ri = r[i];
    float4 e = reinterpret_cast<const float4*>(Eb)[(size_t)i * (NMAX / 4) + j];
    float4 cv = reinterpret_cast<const float4*>(c)[j];
    float4 o;
    o.x = e.x * ri * cv.x; o.y = e.y * ri * cv.y;
    o.z = e.z * ri * cv.z; o.w = e.w * ri * cv.w;
    reinterpret_cast<float4*>(out)[t] = o;
}

// ---------------- host driver ----------------
static inline int cdiv(int a, int b) { return (a + b - 1) / b; }

extern "C" void kernel_launch(void* const* d_in, const int* in_sizes, int n_in,
                              void* d_out, int out_size)
{
    const float* x_s = (const float*)d_in[0];
    const float* x_t = (const float*)d_in[1];
    const int* edges = (const int*)d_in[2];
    const int* edget = (const int*)d_in[3];
    const float* W1[3], *W2[3], *Wr[3], *br[3];
    for (int l = 0; l < 3; l++) {
        W1[l] = (const float*)d_in[4 + 4 * l];
        W2[l] = (const float*)d_in[5 + 4 * l];
        Wr[l] = (const float*)d_in[6 + 4 * l];
        br[l] = (const float*)d_in[7 + 4 * l];
    }
    const float* final_w = (const float*)d_in[16];
    const float* final_b = (const float*)d_in[17];

    const int NS = in_sizes[0] / 128;
    const int NT = in_sizes[1] / 128;
    const int ES = in_sizes[2] / 2;
    const int ET = in_sizes[3] / 2;

    float *Xcat, *tmp1, *tmp2, *agg1, *agg2, *Hb, *Eb, *rr, *cc, *csum, *inv_a, *inv_b;
    int *cnt_a, *cnt_b;
    __nv_bfloat16 *sh, *sl;
    cudaGetSymbolAddress((void**)&Xcat, g_Xcat);
    cudaGetSymbolAddress((void**)&tmp1, g_tmp1);
    cudaGetSymbolAddress((void**)&tmp2, g_tmp2);
    cudaGetSymbolAddress((void**)&agg1, g_agg1);
    cudaGetSymbolAddress((void**)&agg2, g_agg2);
    cudaGetSymbolAddress((void**)&Hb, g_H);
    cudaGetSymbolAddress((void**)&Eb, g_E);
    cudaGetSymbolAddress((void**)&rr, g_r);
    cudaGetSymbolAddress((void**)&cc, g_c);
    cudaGetSymbolAddress((void**)&csum, g_colsum);
    cudaGetSymbolAddress((void**)&cnt_a, g_cnt_a);
    cudaGetSymbolAddress((void**)&cnt_b, g_cnt_b);
    cudaGetSymbolAddress((void**)&inv_a, g_inv_a);
    cudaGetSymbolAddress((void**)&inv_b, g_inv_b);
    cudaGetSymbolAddress((void**)&sh, g_sh);
    cudaGetSymbolAddress((void**)&sl, g_sl);

    for (int gi = 0; gi < 2; gi++) {
        const float* x = gi == 0 ? x_s : x_t;
        const int* ep = gi == 0 ? edges : edget;
        int N = gi == 0 ? NS : NT;
        int E = gi == 0 ? ES : ET;
        const int* src = ep;
        const int* dst = ep + E;
        float* Xc = Xcat + (size_t)gi * NMAX * DCAT;
        float* H = Hb + (size_t)gi * NMAX * DH;

        copy_x<<<cdiv(N * 32, 256), 256>>>(x, Xc, N);
        fill_i<<<cdiv(NMAX, 256), 256>>>(cnt_a, 0, NMAX);
        fill_i<<<cdiv(NMAX, 256), 256>>>(cnt_b, 0, NMAX);
        count_k<<<cdiv(E, 256), 256>>>(dst, cnt_a, E);
        count_k<<<cdiv(E, 256), 256>>>(src, cnt_b, E);
        inv_k<<<cdiv(NMAX, 256), 256>>>(cnt_a, inv_a, NMAX);
        inv_k<<<cdiv(NMAX, 256), 256>>>(cnt_b, inv_b, NMAX);

        int off = 0, fan = 128;
        for (int l = 0; l < 3; l++) {
            const float* hA = Xc + off;
            dim3 grid(4, cdiv(N, 64));
            sgemm<0, 0><<<grid, 256>>>(hA, DCAT, W1[l], DH, tmp1, DH, N, DH, fan,
                                       nullptr, nullptr, nullptr);
            sgemm<0, 0><<<grid, 256>>>(hA, DCAT, W2[l], DH, tmp2, DH, N, DH, fan,
                                       nullptr, nullptr, nullptr);
            fill_f<<<cdiv(N * DH, 256), 256>>>(agg1, 0.f, N * DH);
            fill_f<<<cdiv(N * DH, 256), 256>>>(agg2, 0.f, N * DH);
            scatter_k<<<cdiv(E * 64, 256), 256>>>(tmp1, src, dst, inv_a, agg1, E);
            scatter_k<<<cdiv(E * 64, 256), 256>>>(tmp2, dst, src, inv_b, agg2, E);
            int noff = off + fan;
            sgemm<0, 1><<<grid, 256>>>(hA, DCAT, Wr[l], DH, Xc + noff, DCAT, N, DH, fan,
                                       br[l], agg1, agg2);
            off = noff;
            fan = DH;
        }
        dim3 gridf(4, cdiv(N, 64));
        sgemm<0, 3><<<gridf, 256>>>(Xc, DCAT, final_w, DH, H, DH, N, DH, DCAT,
                                    final_b, nullptr, nullptr);
        l2norm_k<<<N, 256>>>(H);

        // bf16 split (rows >= N are zero -> hi=lo=0, deterministic)
        split_k<<<cdiv(NMAX * DH, 256), 256>>>(H, sh + (size_t)gi * NMAX * DH,
                                               sl + (size_t)gi * NMAX * DH, NMAX * DH);
    }

    // match -> E = exp(20*(Hs_n @ Ht_n^T + 1e-10)) via mma.sync bf16 split-2
    {
        dim3 gm(NMAX / 128, NMAX / 128);
        match_mma_kernel<<<gm, 256>>>(sh, sl,
                                      sh + (size_t)NMAX * DH, sl + (size_t)NMAX * DH, Eb);
        // dummy rows: exp(20*(eps+eps)) == 1.0f in fp32
        fill_f<<<cdiv((NMAX - NS) * NMAX, 256), 256>>>(Eb + (size_t)NS * NMAX, 1.0f,
                                                       (NMAX - NS) * NMAX);
    }

    // sinkhorn via row/col scale factors: 5x (col-norm, row-norm)
    fill_f<<<cdiv(NMAX, 256), 256>>>(rr, 1.0f, NMAX);
    for (int it = 0; it < 5; it++) {
        fill_f<<<cdiv(NMAX, 256), 256>>>(csum, 0.f, NMAX);
        colsum_k<<<dim3(NMAX / 256, 32), 256>>>(Eb, rr, csum);
        recip_k<<<cdiv(NMAX, 256), 256>>>(csum, cc, NMAX);
        rowsum_k<<<NMAX, 256>>>(Eb, cc, rr);
    }
    finalize_k<<<cdiv(NS * (NMAX / 4), 256), 256>>>(Eb, rr, cc, (float*)d_out, NS);
}

// round 4
// speedup vs baseline: 1.1199x; 1.0291x over previous
#include <cuda_runtime.h>
#include <cuda_bf16.h>
#include <math.h>
#include <stdint.h>

#define NMAX 4096
#define DH   256
#define DCAT 896
#define WTOT 720896   // total transposed-weight elems

// ---------------- scratch (device globals; no runtime alloc) ----------------
__device__ __align__(16) __nv_bfloat16 g_Xh[2][(size_t)NMAX * DCAT];
__device__ __align__(16) __nv_bfloat16 g_Xl[2][(size_t)NMAX * DCAT];
__device__ __align__(16) __nv_bfloat16 g_Wth[WTOT];
__device__ __align__(16) __nv_bfloat16 g_Wtl[WTOT];
__device__ __align__(16) float g_tmp1[(size_t)NMAX * DH];
__device__ __align__(16) float g_tmp2[(size_t)NMAX * DH];
__device__ __align__(16) float g_agg1[(size_t)NMAX * DH];
__device__ __align__(16) float g_agg2[(size_t)NMAX * DH];
__device__ __align__(16) float g_H[(size_t)NMAX * DH];
__device__ __align__(16) float g_E[(size_t)NMAX * NMAX];   // exp(20*(match+eps)), 64MB
__device__ __align__(16) float g_r[NMAX];
__device__ __align__(16) float g_c[NMAX];
__device__ __align__(16) float g_colsum[NMAX];
__device__ __align__(16) int   g_cnt_a[NMAX];
__device__ __align__(16) int   g_cnt_b[NMAX];
__device__ __align__(16) float g_inv_a[NMAX];
__device__ __align__(16) float g_inv_b[NMAX];
// bf16 split copies of normalized H for match GEMM
__device__ __align__(16) __nv_bfloat16 g_sh[2][(size_t)NMAX * DH];
__device__ __align__(16) __nv_bfloat16 g_sl[2][(size_t)NMAX * DH];

// ---------------- small utility kernels ----------------
__global__ void fill_f(float* p, float v, int n) {
    int t = blockIdx.x * blockDim.x + threadIdx.x;
    if (t < n) p[t] = v;
}
__global__ void fill_i(int* p, int v, int n) {
    int t = blockIdx.x * blockDim.x + threadIdx.x;
    if (t < n) p[t] = v;
}
__global__ void count_k(const int* __restrict__ idx, int* __restrict__ cnt, int E) {
    int t = blockIdx.x * blockDim.x + threadIdx.x;
    if (t < E) atomicAdd(&cnt[idx[t]], 1);
}
__global__ void inv_k(const int* __restrict__ cnt, float* __restrict__ inv, int n) {
    int t = blockIdx.x * blockDim.x + threadIdx.x;
    if (t < n) inv[t] = 1.0f / (float)max(cnt[t], 1);
}
__global__ void recip_k(const float* __restrict__ a, float* __restrict__ b, int n) {
    int t = blockIdx.x * blockDim.x + threadIdx.x;
    if (t < n) b[t] = 1.0f / a[t];
}
// input features -> bf16 hi/lo directly into Xsplit cols 0..127
__global__ void copyx_split(const float* __restrict__ x, __nv_bfloat16* __restrict__ Xh,
                            __nv_bfloat16* __restrict__ Xl, int N)
{
    int t = blockIdx.x * blockDim.x + threadIdx.x;
    if (t >= N * 128) return;
    int row = t >> 7, c = t & 127;
    float v = x[t];
    __nv_bfloat16 h = __float2bfloat16(v);
    float r = v - __bfloat162float(h);
    Xh[(size_t)row * DCAT + c] = h;
    Xl[(size_t)row * DCAT + c] = __float2bfloat16(r);
}
// transpose W [K][N] -> [N][K] bf16 hi/lo
__global__ void wtsplit_k(const float* __restrict__ W, __nv_bfloat16* __restrict__ th,
                          __nv_bfloat16* __restrict__ tl, int K, int N)
{
    int t = blockIdx.x * blockDim.x + threadIdx.x;
    if (t >= K * N) return;
    int k = t / N, n = t % N;
    float v = W[t];
    __nv_bfloat16 h = __float2bfloat16(v);
    float r = v - __bfloat162float(h);
    th[(size_t)n * K + k] = h;
    tl[(size_t)n * K + k] = __float2bfloat16(r);
}

// ---------------- mma.sync bf16 helpers (baseline PTX, no arch-'a' features) --
__device__ __forceinline__ uint32_t smem_u32(const void* p) {
    uint32_t a;
    asm("{ .reg .u64 t; cvta.to.shared.u64 t, %1; cvt.u32.u64 %0, t; }" : "=r"(a) : "l"(p));
    return a;
}
__device__ __forceinline__ void ldm_x4(uint32_t* r, uint32_t addr) {
    asm volatile("ldmatrix.sync.aligned.m8n8.x4.shared.b16 {%0,%1,%2,%3}, [%4];"
        : "=r"(r[0]), "=r"(r[1]), "=r"(r[2]), "=r"(r[3]) : "r"(addr));
}
__device__ __forceinline__ void mma_bf16(float* d, const uint32_t* a, uint32_t b0, uint32_t b1) {
    asm volatile(
        "mma.sync.aligned.m16n8k16.row.col.f32.bf16.bf16.f32 "
        "{%0,%1,%2,%3}, {%4,%5,%6,%7}, {%8,%9}, {%0,%1,%2,%3};"
        : "+f"(d[0]), "+f"(d[1]), "+f"(d[2]), "+f"(d[3])
        : "r"(a[0]), "r"(a[1]), "r"(a[2]), "r"(a[3]), "r"(b0), "r"(b1));
}

// ---------------- generic GNN GEMM: C[m][n] = sum_k A[m][k] * Bt[n][k] ------
// split-2 bf16: Ah*Bh + Ah*Bl + Al*Bh, fp32 accum. N fixed 256 via grid.
// CTA 64x64 tile, 128 thr = 4 warps (2m x 2n), warp 32x32 = 2x4 m16n8k16.
// EPI 0: store fp32 C (ldc)
// EPI 1: v = relu(acc + bias[n] + add1[m*DH+n] + add2[m*DH+n]); store bf16 hi/lo (ldc)
// EPI 3: v = acc + bias[n]; store fp32 C (ldc)
#define GSP 40

template <int EPI>
__global__ void __launch_bounds__(128) gemm_mma(
    const __nv_bfloat16* __restrict__ Ah, const __nv_bfloat16* __restrict__ Al, int lda,
    const __nv_bfloat16* __restrict__ Bh, const __nv_bfloat16* __restrict__ Bl,
    float* __restrict__ C, int ldc, int M, int K,
    const float* __restrict__ bias, const float* __restrict__ add1,
    const float* __restrict__ add2,
    __nv_bfloat16* __restrict__ Oh, __nv_bfloat16* __restrict__ Ol)
{
    __shared__ __nv_bfloat16 sA[64 * GSP];
    __shared__ __nv_bfloat16 sB[64 * GSP];
    const int tid = threadIdx.x;
    const int lane = tid & 31, wid = tid >> 5;
    const int wm = wid & 1, wn = wid >> 1;
    const int row0 = blockIdx.y * 64, col0 = blockIdx.x * 64;

    float acc[2][4][4];
    #pragma unroll
    for (int i = 0; i < 2; i++)
        #pragma unroll
        for (int j = 0; j < 4; j++)
            #pragma unroll
            for (int q = 0; q < 4; q++) acc[i][j][q] = 0.f;

    const int a_row = wm * 32 + (lane < 16 ? lane : lane - 16);
    const int a_col = (lane < 16 ? 0 : 8);
    const int b_row = wn * 32 + (lane & 7);
    const int b_col = (lane >> 3) * 8;

    #pragma unroll
    for (int p = 0; p < 3; p++) {
        const __nv_bfloat16* Ag = (p == 2 ? Al : Ah) + (size_t)row0 * lda;
        const __nv_bfloat16* Bg = (p == 1 ? Bl : Bh) + (size_t)col0 * K;
        for (int kc = 0; kc < K / 32; kc++) {
            __syncthreads();
            // 64x32 bf16 tiles = 256 uint4 each; 2 per thread per tile
            #pragma unroll
            for (int r = 0; r < 2; r++) {
                int idx = tid * 2 + r;
                int row = idx >> 2, q = idx & 3;
                *reinterpret_cast<uint4*>(sA + row * GSP + q * 8) =
                    *reinterpret_cast<const uint4*>(Ag + (size_t)row * lda + kc * 32 + q * 8);
                *reinterpret_cast<uint4*>(sB + row * GSP + q * 8) =
                    *reinterpret_cast<const uint4*>(Bg + (size_t)row * K + kc * 32 + q * 8);
            }
            __syncthreads();

            uint32_t bfr[4][4];
            #pragma unroll
            for (int j = 0; j < 4; j++)
                ldm_x4(bfr[j], smem_u32(sB + (b_row + j * 8) * GSP + b_col));

            #pragma unroll
            for (int h = 0; h < 2; h++) {
                #pragma unroll
                for (int i = 0; i < 2; i++) {
                    uint32_t afr[4];
                    ldm_x4(afr, smem_u32(sA + (a_row + i * 16) * GSP + h * 16 + a_col));
                    #pragma unroll
                    for (int j = 0; j < 4; j++)
                        mma_bf16(acc[i][j], afr, bfr[j][2 * h], bfr[j][2 * h + 1]);
                }
            }
        }
    }

    const int er = lane >> 2, ec = (lane & 3) * 2;
    #pragma unroll
    for (int i = 0; i < 2; i++) {
        #pragma unroll
        for (int j = 0; j < 4; j++) {
            int gc = col0 + wn * 32 + j * 8 + ec;
            #pragma unroll
            for (int rr = 0; rr < 2; rr++) {
                int row = row0 + wm * 32 + i * 16 + er + rr * 8;
                if (row >= M) continue;
                float v0 = acc[i][j][2 * rr + 0];
                float v1 = acc[i][j][2 * rr + 1];
                if (EPI == 0) {
                    *reinterpret_cast<float2*>(C + (size_t)row * ldc + gc) =
                        make_float2(v0, v1);
                } else if (EPI == 1) {
                    v0 = fmaxf(v0 + bias[gc] + add1[(size_t)row * DH + gc]
                                  + add2[(size_t)row * DH + gc], 0.f);
                    v1 = fmaxf(v1 + bias[gc + 1] + add1[(size_t)row * DH + gc + 1]
                                  + add2[(size_t)row * DH + gc + 1], 0.f);
                    __nv_bfloat16 h0 = __float2bfloat16(v0);
                    __nv_bfloat16 h1 = __float2bfloat16(v1);
                    __nv_bfloat16 l0 = __float2bfloat16(v0 - __bfloat162float(h0));
                    __nv_bfloat16 l1 = __float2bfloat16(v1 - __bfloat162float(h1));
                    __nv_bfloat162 hv; hv.x = h0; hv.y = h1;
                    __nv_bfloat162 lv; lv.x = l0; lv.y = l1;
                    *reinterpret_cast<__nv_bfloat162*>(Oh + (size_t)row * ldc + gc) = hv;
                    *reinterpret_cast<__nv_bfloat162*>(Ol + (size_t)row * ldc + gc) = lv;
                } else {  // EPI == 3
                    *reinterpret_cast<float2*>(C + (size_t)row * ldc + gc) =
                        make_float2(v0 + bias[gc], v1 + bias[gc + 1]);
                }
            }
        }
    }
}

// ---------------- tensor-core match GEMM (split-2 bf16) ----------------
#define SPAD 40

__global__ void __launch_bounds__(256, 2) match_mma_kernel(
    const __nv_bfloat16* __restrict__ Ah, const __nv_bfloat16* __restrict__ Al,
    const __nv_bfloat16* __restrict__ Bh, const __nv_bfloat16* __restrict__ Bl,
    float* __restrict__ Eout)
{
    __shared__ __nv_bfloat16 sA[128 * SPAD];
    __shared__ __nv_bfloat16 sB[128 * SPAD];
    const int tid = threadIdx.x;
    const int wid = tid >> 5, lane = tid & 31;
    const int wm = wid & 3, wn = wid >> 2;
    const int row0 = blockIdx.y * 128, col0 = blockIdx.x * 128;

    float acc[2][8][4];
    #pragma unroll
    for (int i = 0; i < 2; i++)
        #pragma unroll
        for (int j = 0; j < 8; j++)
            #pragma unroll
            for (int q = 0; q < 4; q++) acc[i][j][q] = 0.f;

    const int a_row = wm * 32 + (lane < 16 ? lane : lane - 16);
    const int a_col = (lane < 16 ? 0 : 8);
    const int b_row = wn * 64 + (lane & 7);
    const int b_col = (lane >> 3) * 8;

    #pragma unroll
    for (int p = 0; p < 3; p++) {
        const __nv_bfloat16* Ag = (p == 2 ? Al : Ah) + (size_t)row0 * DH;
        const __nv_bfloat16* Bg = (p == 1 ? Bl : Bh) + (size_t)col0 * DH;
        for (int kc = 0; kc < DH / 32; kc++) {
            __syncthreads();
            #pragma unroll
            for (int r = 0; r < 2; r++) {
                int idx = tid * 2 + r;
                int row = idx >> 2, q = idx & 3;
                *reinterpret_cast<uint4*>(sA + row * SPAD + q * 8) =
                    *reinterpret_cast<const uint4*>(Ag + (size_t)row * DH + kc * 32 + q * 8);
                *reinterpret_cast<uint4*>(sB + row * SPAD + q * 8) =
                    *reinterpret_cast<const uint4*>(Bg + (size_t)row * DH + kc * 32 + q * 8);
            }
            __syncthreads();

            uint32_t bfr[8][4];
            #pragma unroll
            for (int j = 0; j < 8; j++)
                ldm_x4(bfr[j], smem_u32(sB + (b_row + j * 8) * SPAD + b_col));

            #pragma unroll
            for (int h = 0; h < 2; h++) {
                #pragma unroll
                for (int i = 0; i < 2; i++) {
                    uint32_t afr[4];
                    ldm_x4(afr, smem_u32(sA + (a_row + i * 16) * SPAD + h * 16 + a_col));
                    #pragma unroll
                    for (int j = 0; j < 8; j++)
                        mma_bf16(acc[i][j], afr, bfr[j][2 * h], bfr[j][2 * h + 1]);
                }
            }
        }
    }

    const int er = lane >> 2, ec = (lane & 3) * 2;
    #pragma unroll
    for (int i = 0; i < 2; i++) {
        int gr0 = row0 + wm * 32 + i * 16 + er;
        #pragma unroll
        for (int j = 0; j < 8; j++) {
            int gc = col0 + wn * 64 + j * 8 + ec;
            float2 o0, o1;
            o0.x = __expf(20.f * (acc[i][j][0] + 1e-10f));
            o0.y = __expf(20.f * (acc[i][j][1] + 1e-10f));
            o1.x = __expf(20.f * (acc[i][j][2] + 1e-10f));
            o1.y = __expf(20.f * (acc[i][j][3] + 1e-10f));
            *reinterpret_cast<float2*>(Eout + (size_t)gr0 * NMAX + gc) = o0;
            *reinterpret_cast<float2*>(Eout + (size_t)(gr0 + 8) * NMAX + gc) = o1;
        }
    }
}

// ---------------- scatter-mean (sum with pre-scaled 1/count) ----------------
__global__ void scatter_k(const float* __restrict__ vals,
                          const int* __restrict__ gidx,
                          const int* __restrict__ sidx,
                          const float* __restrict__ invc,
                          float* __restrict__ out, int E)
{
    int t = blockIdx.x * blockDim.x + threadIdx.x;
    int e = t >> 6;
    int d = (t & 63) << 2;
    if (e >= E) return;
    int g = gidx[e], s = sidx[e];
    float sc = invc[s];
    float4 v = *reinterpret_cast<const float4*>(vals + (size_t)g * DH + d);
    float* o = out + (size_t)s * DH + d;
    atomicAdd(o + 0, v.x * sc);
    atomicAdd(o + 1, v.y * sc);
    atomicAdd(o + 2, v.z * sc);
    atomicAdd(o + 3, v.w * sc);
}

// ---------------- fused row L2 normalize + bf16 split ----------------
__global__ void l2split_k(const float* __restrict__ H, __nv_bfloat16* __restrict__ sh,
                          __nv_bfloat16* __restrict__ sl)
{
    int row = blockIdx.x;
    int tid = threadIdx.x;
    float v = H[(size_t)row * DH + tid];
    __shared__ float red[256];
    red[tid] = v * v;
    __syncthreads();
    for (int s = 128; s > 0; s >>= 1) {
        if (tid < s) red[tid] += red[tid + s];
        __syncthreads();
    }
    float sc = 1.0f / fmaxf(sqrtf(red[0]), 1e-12f);
    float nv = v * sc;
    __nv_bfloat16 h = __float2bfloat16(nv);
    float r = nv - __bfloat162float(h);
    sh[(size_t)row * DH + tid] = h;
    sl[(size_t)row * DH + tid] = __float2bfloat16(r);
}

// ---------------- sinkhorn factor passes ----------------
__global__ void colsum_k(const float* __restrict__ Eb, const float* __restrict__ r,
                         float* __restrict__ cs)
{
    int j = blockIdx.x * 256 + threadIdx.x;
    int i0 = blockIdx.y * 128;
    float acc = 0.f;
    #pragma unroll 4
    for (int i = 0; i < 128; i++)
        acc += Eb[(size_t)(i0 + i) * NMAX + j] * __ldg(&r[i0 + i]);
    atomicAdd(&cs[j], acc);
}

__global__ void rowsum_k(const float* __restrict__ Eb, const float* __restrict__ c,
                         float* __restrict__ r)
{
    int i = blockIdx.x, tid = threadIdx.x;
    const float4* row = reinterpret_cast<const float4*>(Eb + (size_t)i * NMAX);
    const float4* c4 = reinterpret_cast<const float4*>(c);
    float acc = 0.f;
    for (int j = tid; j < NMAX / 4; j += 256) {
        float4 e = row[j], cv = c4[j];
        acc += e.x * cv.x + e.y * cv.y + e.z * cv.z + e.w * cv.w;
    }
    __shared__ float red[256];
    red[tid] = acc;
    __syncthreads();
    for (int s = 128; s > 0; s >>= 1) {
        if (tid < s) red[tid] += red[tid + s];
        __syncthreads();
    }
    if (tid == 0) r[i] = 1.0f / red[0];
}

__global__ void finalize_k(const float* __restrict__ Eb, const float* __restrict__ r,
                           const float* __restrict__ c, float* __restrict__ out, int rows)
{
    int t = blockIdx.x * blockDim.x + threadIdx.x;
    if (t >= rows * (NMAX / 4)) return;
    int i = t >> 10, j = t & 1023;
    float ri = r[i];
    float4 e = reinterpret_cast<const float4*>(Eb)[(size_t)i * (NMAX / 4) + j];
    float4 cv = reinterpret_cast<const float4*>(c)[j];
    float4 o;
    o.x = e.x * ri * cv.x; o.y = e.y * ri * cv.y;
    o.z = e.z * ri * cv.z; o.w = e.w * ri * cv.w;
    reinterpret_cast<float4*>(out)[t] = o;
}

// ---------------- host driver ----------------
static inline int cdiv(int a, int b) { return (a + b - 1) / b; }

extern "C" void kernel_launch(void* const* d_in, const int* in_sizes, int n_in,
                              void* d_out, int out_size)
{
    const float* x_s = (const float*)d_in[0];
    const float* x_t = (const float*)d_in[1];
    const int* edges = (const int*)d_in[2];
    const int* edget = (const int*)d_in[3];
    const float* W1[3], *W2[3], *Wr[3], *br[3];
    for (int l = 0; l < 3; l++) {
        W1[l] = (const float*)d_in[4 + 4 * l];
        W2[l] = (const float*)d_in[5 + 4 * l];
        Wr[l] = (const float*)d_in[6 + 4 * l];
        br[l] = (const float*)d_in[7 + 4 * l];
    }
    const float* final_w = (const float*)d_in[16];
    const float* final_b = (const float*)d_in[17];

    const int NS = in_sizes[0] / 128;
    const int NT = in_sizes[1] / 128;
    const int ES = in_sizes[2] / 2;
    const int ET = in_sizes[3] / 2;

    float *tmp1, *tmp2, *agg1, *agg2, *Hf, *Eb, *rr, *cc, *csum, *inv_a, *inv_b;
    int *cnt_a, *cnt_b;
    __nv_bfloat16 *Xh, *Xl, *Wth, *Wtl, *sh, *sl;
    cudaGetSymbolAddress((void**)&Xh, g_Xh);
    cudaGetSymbolAddress((void**)&Xl, g_Xl);
    cudaGetSymbolAddress((void**)&Wth, g_Wth);
    cudaGetSymbolAddress((void**)&Wtl, g_Wtl);
    cudaGetSymbolAddress((void**)&tmp1, g_tmp1);
    cudaGetSymbolAddress((void**)&tmp2, g_tmp2);
    cudaGetSymbolAddress((void**)&agg1, g_agg1);
    cudaGetSymbolAddress((void**)&agg2, g_agg2);
    cudaGetSymbolAddress((void**)&Hf, g_H);
    cudaGetSymbolAddress((void**)&Eb, g_E);
    cudaGetSymbolAddress((void**)&rr, g_r);
    cudaGetSymbolAddress((void**)&cc, g_c);
    cudaGetSymbolAddress((void**)&csum, g_colsum);
    cudaGetSymbolAddress((void**)&cnt_a, g_cnt_a);
    cudaGetSymbolAddress((void**)&cnt_b, g_cnt_b);
    cudaGetSymbolAddress((void**)&inv_a, g_inv_a);
    cudaGetSymbolAddress((void**)&inv_b, g_inv_b);
    cudaGetSymbolAddress((void**)&sh, g_sh);
    cudaGetSymbolAddress((void**)&sl, g_sl);

    // ---- transpose+split all weights ----
    // offsets (elems): layer0 W1/W2/Wr @ 0/32768/65536, layer1 @ 98304+.., etc.
    int woff[10];
    {
        int o = 0, fan = 128;
        for (int l = 0; l < 3; l++) {
            for (int w = 0; w < 3; w++) { woff[l * 3 + w] = o; o += fan * DH; }
            fan = DH;
        }
        woff[9] = o;  // final_w: 896*256
    }
    for (int l = 0; l < 3; l++) {
        int fan = (l == 0) ? 128 : DH;
        const float* ws[3] = { W1[l], W2[l], Wr[l] };
        for (int w = 0; w < 3; w++)
            wtsplit_k<<<cdiv(fan * DH, 256), 256>>>(ws[w], Wth + woff[l * 3 + w],
                                                    Wtl + woff[l * 3 + w], fan, DH);
    }
    wtsplit_k<<<cdiv(DCAT * DH, 256), 256>>>(final_w, Wth + woff[9], Wtl + woff[9],
                                             DCAT, DH);

    for (int gi = 0; gi < 2; gi++) {
        const float* x = gi == 0 ? x_s : x_t;
        const int* ep = gi == 0 ? edges : edget;
        int N = gi == 0 ? NS : NT;
        int E = gi == 0 ? ES : ET;
        const int* src = ep;
        const int* dst = ep + E;
        __nv_bfloat16* Xgh = Xh + (size_t)gi * NMAX * DCAT;
        __nv_bfloat16* Xgl = Xl + (size_t)gi * NMAX * DCAT;

        copyx_split<<<cdiv(N * 128, 256), 256>>>(x, Xgh, Xgl, N);
        fill_i<<<cdiv(NMAX, 256), 256>>>(cnt_a, 0, NMAX);
        fill_i<<<cdiv(NMAX, 256), 256>>>(cnt_b, 0, NMAX);
        count_k<<<cdiv(E, 256), 256>>>(dst, cnt_a, E);
        count_k<<<cdiv(E, 256), 256>>>(src, cnt_b, E);
        inv_k<<<cdiv(NMAX, 256), 256>>>(cnt_a, inv_a, NMAX);
        inv_k<<<cdiv(NMAX, 256), 256>>>(cnt_b, inv_b, NMAX);

        int off = 0, fan = 128;
        for (int l = 0; l < 3; l++) {
            const __nv_bfloat16* Ahp = Xgh + off;
            const __nv_bfloat16* Alp = Xgl + off;
            dim3 grid(DH / 64, cdiv(N, 64));
            gemm_mma<0><<<grid, 128>>>(Ahp, Alp, DCAT,
                                       Wth + woff[l * 3 + 0], Wtl + woff[l * 3 + 0],
                                       tmp1, DH, N, fan, nullptr, nullptr, nullptr,
                                       nullptr, nullptr);
            gemm_mma<0><<<grid, 128>>>(Ahp, Alp, DCAT,
                                       Wth + woff[l * 3 + 1], Wtl + woff[l * 3 + 1],
                                       tmp2, DH, N, fan, nullptr, nullptr, nullptr,
                                       nullptr, nullptr);
            fill_f<<<cdiv(N * DH, 256), 256>>>(agg1, 0.f, N * DH);
            fill_f<<<cdiv(N * DH, 256), 256>>>(agg2, 0.f, N * DH);
            scatter_k<<<cdiv(E * 64, 256), 256>>>(tmp1, src, dst, inv_a, agg1, E);
            scatter_k<<<cdiv(E * 64, 256), 256>>>(tmp2, dst, src, inv_b, agg2, E);
            int noff = off + fan;   // 0->128, 128->384, 384->640
            gemm_mma<1><<<grid, 128>>>(Ahp, Alp, DCAT,
                                       Wth + woff[l * 3 + 2], Wtl + woff[l * 3 + 2],
                                       nullptr, DCAT, N, fan, br[l], agg1, agg2,
                                       Xgh + noff, Xgl + noff);
            off = noff;
            fan = DH;
        }
        // final linear: H = Xcat @ final_w + final_b (K = 896)
        dim3 gridf(DH / 64, cdiv(N, 64));
        gemm_mma<3><<<gridf, 128>>>(Xgh, Xgl, DCAT, Wth + woff[9], Wtl + woff[9],
                                    Hf, DH, N, DCAT, final_b, nullptr, nullptr,
                                    nullptr, nullptr);
        l2split_k<<<N, 256>>>(Hf, sh + (size_t)gi * NMAX * DH,
                              sl + (size_t)gi * NMAX * DH);
    }

    // match -> E = exp(20*(Hs_n @ Ht_n^T + 1e-10)) via mma.sync bf16 split-2
    {
        dim3 gm(NMAX / 128, NMAX / 128);
        match_mma_kernel<<<gm, 256>>>(sh, sl,
                                      sh + (size_t)NMAX * DH, sl + (size_t)NMAX * DH, Eb);
        // dummy rows: exp(20*(eps+eps)) == 1.0f in fp32
        fill_f<<<cdiv((NMAX - NS) * NMAX, 256), 256>>>(Eb + (size_t)NS * NMAX, 1.0f,
                                                       (NMAX - NS) * NMAX);
    }

    // sinkhorn via row/col scale factors: 5x (col-norm, row-norm)
    fill_f<<<cdiv(NMAX, 256), 256>>>(rr, 1.0f, NMAX);
    for (int it = 0; it < 5; it++) {
        fill_f<<<cdiv(NMAX, 256), 256>>>(csum, 0.f, NMAX);
        colsum_k<<<dim3(NMAX / 256, 32), 256>>>(Eb, rr, csum);
        recip_k<<<cdiv(NMAX, 256), 256>>>(csum, cc, NMAX);
        rowsum_k<<<NMAX, 256>>>(Eb, cc, rr);
    }
    finalize_k<<<cdiv(NS * (NMAX / 4), 256), 256>>>(Eb, rr, cc, (float*)d_out, NS);
}

// round 5
// speedup vs baseline: 1.5476x; 1.3820x over previous
#include <cuda_runtime.h>
#include <cuda_bf16.h>
#include <math.h>
#include <stdint.h>

#define NMAX 4096
#define DH   256
#define DCAT 896
#define EMAX 65536
#define WTOT 720896   // total transposed-weight elems

// ---------------- scratch (device globals; no runtime alloc) ----------------
__device__ __align__(16) __nv_bfloat16 g_Xh[2][(size_t)NMAX * DCAT];
__device__ __align__(16) __nv_bfloat16 g_Xl[2][(size_t)NMAX * DCAT];
__device__ __align__(16) __nv_bfloat16 g_Wth[WTOT];
__device__ __align__(16) __nv_bfloat16 g_Wtl[WTOT];
__device__ __align__(16) float g_tmp1[(size_t)NMAX * DH];
__device__ __align__(16) float g_tmp2[(size_t)NMAX * DH];
__device__ __align__(16) float g_agg1[(size_t)NMAX * DH];
__device__ __align__(16) float g_agg2[(size_t)NMAX * DH];
__device__ __align__(16) float g_H[(size_t)NMAX * DH];
__device__ __align__(16) float g_E[(size_t)NMAX * NMAX];   // exp(20*(match+eps)), 64MB
__device__ __align__(16) float g_r[NMAX];
__device__ __align__(16) float g_c[NMAX];
__device__ __align__(16) float g_colsum[NMAX];
__device__ __align__(16) int   g_cnt_a[NMAX];
__device__ __align__(16) int   g_cnt_b[NMAX];
__device__ __align__(16) float g_inv_a[NMAX];
__device__ __align__(16) float g_inv_b[NMAX];
// CSR structures (per graph, rebuilt)
__device__ __align__(16) int g_off_a[NMAX];
__device__ __align__(16) int g_off_b[NMAX];
__device__ __align__(16) int g_cur_a[NMAX];
__device__ __align__(16) int g_cur_b[NMAX];
__device__ __align__(16) int g_lst_a[EMAX];
__device__ __align__(16) int g_lst_b[EMAX];
// bf16 split copies of normalized H for match GEMM
__device__ __align__(16) __nv_bfloat16 g_sh[2][(size_t)NMAX * DH];
__device__ __align__(16) __nv_bfloat16 g_sl[2][(size_t)NMAX * DH];

// ---------------- small utility kernels ----------------
__global__ void fill_f(float* p, float v, int n) {
    int t = blockIdx.x * blockDim.x + threadIdx.x;
    if (t < n) p[t] = v;
}
__global__ void fill_i(int* p, int v, int n) {
    int t = blockIdx.x * blockDim.x + threadIdx.x;
    if (t < n) p[t] = v;
}
__global__ void count_k(const int* __restrict__ idx, int* __restrict__ cnt, int E) {
    int t = blockIdx.x * blockDim.x + threadIdx.x;
    if (t < E) atomicAdd(&cnt[idx[t]], 1);
}
__global__ void inv_k(const int* __restrict__ cnt, float* __restrict__ inv, int n) {
    int t = blockIdx.x * blockDim.x + threadIdx.x;
    if (t < n) inv[t] = 1.0f / (float)max(cnt[t], 1);
}
__global__ void recip_k(const float* __restrict__ a, float* __restrict__ b, int n) {
    int t = blockIdx.x * blockDim.x + threadIdx.x;
    if (t < n) b[t] = 1.0f / a[t];
}

// exclusive scan over NMAX counts -> off, cur (single block, 1024 thr)
__global__ void scan_k(const int* __restrict__ cnt, int* __restrict__ off,
                       int* __restrict__ cur)
{
    __shared__ int s[NMAX];
    int tid = threadIdx.x;
    #pragma unroll
    for (int j = 0; j < 4; j++) s[tid + j * 1024] = cnt[tid + j * 1024];
    __syncthreads();
    for (int d = 1; d < NMAX; d <<= 1) {
        int v[4];
        #pragma unroll
        for (int j = 0; j < 4; j++) {
            int i = tid + j * 1024;
            v[j] = (i >= d) ? s[i - d] : 0;
        }
        __syncthreads();
        #pragma unroll
        for (int j = 0; j < 4; j++) s[tid + j * 1024] += v[j];
        __syncthreads();
    }
    #pragma unroll
    for (int j = 0; j < 4; j++) {
        int i = tid + j * 1024;
        int o = s[i] - cnt[i];
        off[i] = o;
        cur[i] = o;
    }
}

// place edges into CSR slots: lst[slot(key)] = val
__global__ void place_k(const int* __restrict__ key, const int* __restrict__ val,
                        int* __restrict__ cur, int* __restrict__ lst, int E)
{
    int t = blockIdx.x * blockDim.x + threadIdx.x;
    if (t >= E) return;
    int k = key[t];
    int p = atomicAdd(&cur[k], 1);
    lst[p] = val[t];
}

// CSR gather-mean: out[n][tid] = inv[n] * sum_{e in list(n)} vals[lst[e]][tid]
__global__ void __launch_bounds__(256) gather_k(
    const float* __restrict__ vals, const int* __restrict__ off,
    const int* __restrict__ cnt, const float* __restrict__ inv,
    const int* __restrict__ lst, float* __restrict__ out)
{
    __shared__ int sl[64];
    const int n = blockIdx.x;
    const int tid = threadIdx.x;
    const int beg = off[n];
    const int d = cnt[n];
    float acc = 0.f;
    for (int base = 0; base < d; base += 64) {
        int chunk = min(64, d - base);
        if (tid < 64 && tid < chunk) sl[tid] = lst[beg + base + tid];
        __syncthreads();
        int e = 0;
        for (; e + 4 <= chunk; e += 4) {
            int s0 = sl[e], s1 = sl[e + 1], s2 = sl[e + 2], s3 = sl[e + 3];
            float v0 = vals[(size_t)s0 * DH + tid];
            float v1 = vals[(size_t)s1 * DH + tid];
            float v2 = vals[(size_t)s2 * DH + tid];
            float v3 = vals[(size_t)s3 * DH + tid];
            acc += (v0 + v1) + (v2 + v3);
        }
        for (; e < chunk; e++)
            acc += vals[(size_t)sl[e] * DH + tid];
        __syncthreads();
    }
    out[(size_t)n * DH + tid] = acc * inv[n];
}

// input features -> bf16 hi/lo directly into Xsplit cols 0..127
__global__ void copyx_split(const float* __restrict__ x, __nv_bfloat16* __restrict__ Xh,
                            __nv_bfloat16* __restrict__ Xl, int N)
{
    int t = blockIdx.x * blockDim.x + threadIdx.x;
    if (t >= N * 128) return;
    int row = t >> 7, c = t & 127;
    float v = x[t];
    __nv_bfloat16 h = __float2bfloat16(v);
    float r = v - __bfloat162float(h);
    Xh[(size_t)row * DCAT + c] = h;
    Xl[(size_t)row * DCAT + c] = __float2bfloat16(r);
}
// transpose W [K][N] -> [N][K] bf16 hi/lo
__global__ void wtsplit_k(const float* __restrict__ W, __nv_bfloat16* __restrict__ th,
                          __nv_bfloat16* __restrict__ tl, int K, int N)
{
    int t = blockIdx.x * blockDim.x + threadIdx.x;
    if (t >= K * N) return;
    int k = t / N, n = t % N;
    float v = W[t];
    __nv_bfloat16 h = __float2bfloat16(v);
    float r = v - __bfloat162float(h);
    th[(size_t)n * K + k] = h;
    tl[(size_t)n * K + k] = __float2bfloat16(r);
}

// ---------------- mma.sync bf16 helpers ----------------
__device__ __forceinline__ uint32_t smem_u32(const void* p) {
    uint32_t a;
    asm("{ .reg .u64 t; cvta.to.shared.u64 t, %1; cvt.u32.u64 %0, t; }" : "=r"(a) : "l"(p));
    return a;
}
__device__ __forceinline__ void ldm_x4(uint32_t* r, uint32_t addr) {
    asm volatile("ldmatrix.sync.aligned.m8n8.x4.shared.b16 {%0,%1,%2,%3}, [%4];"
        : "=r"(r[0]), "=r"(r[1]), "=r"(r[2]), "=r"(r[3]) : "r"(addr));
}
__device__ __forceinline__ void mma_bf16(float* d, const uint32_t* a, uint32_t b0, uint32_t b1) {
    asm volatile(
        "mma.sync.aligned.m16n8k16.row.col.f32.bf16.bf16.f32 "
        "{%0,%1,%2,%3}, {%4,%5,%6,%7}, {%8,%9}, {%0,%1,%2,%3};"
        : "+f"(d[0]), "+f"(d[1]), "+f"(d[2]), "+f"(d[3])
        : "r"(a[0]), "r"(a[1]), "r"(a[2]), "r"(a[3]), "r"(b0), "r"(b1));
}

// ---------------- generic GNN GEMM (split-2 bf16) ----------------
#define GSP 40

template <int EPI>
__global__ void __launch_bounds__(128) gemm_mma(
    const __nv_bfloat16* __restrict__ Ah, const __nv_bfloat16* __restrict__ Al, int lda,
    const __nv_bfloat16* __restrict__ Bh, const __nv_bfloat16* __restrict__ Bl,
    float* __restrict__ C, int ldc, int M, int K,
    const float* __restrict__ bias, const float* __restrict__ add1,
    const float* __restrict__ add2,
    __nv_bfloat16* __restrict__ Oh, __nv_bfloat16* __restrict__ Ol)
{
    __shared__ __nv_bfloat16 sA[64 * GSP];
    __shared__ __nv_bfloat16 sB[64 * GSP];
    const int tid = threadIdx.x;
    const int lane = tid & 31, wid = tid >> 5;
    const int wm = wid & 1, wn = wid >> 1;
    const int row0 = blockIdx.y * 64, col0 = blockIdx.x * 64;

    float acc[2][4][4];
    #pragma unroll
    for (int i = 0; i < 2; i++)
        #pragma unroll
        for (int j = 0; j < 4; j++)
            #pragma unroll
            for (int q = 0; q < 4; q++) acc[i][j][q] = 0.f;

    const int a_row = wm * 32 + (lane < 16 ? lane : lane - 16);
    const int a_col = (lane < 16 ? 0 : 8);
    const int b_row = wn * 32 + (lane & 7);
    const int b_col = (lane >> 3) * 8;

    #pragma unroll
    for (int p = 0; p < 3; p++) {
        const __nv_bfloat16* Ag = (p == 2 ? Al : Ah) + (size_t)row0 * lda;
        const __nv_bfloat16* Bg = (p == 1 ? Bl : Bh) + (size_t)col0 * K;
        for (int kc = 0; kc < K / 32; kc++) {
            __syncthreads();
            #pragma unroll
            for (int r = 0; r < 2; r++) {
                int idx = tid * 2 + r;
                int row = idx >> 2, q = idx & 3;
                *reinterpret_cast<uint4*>(sA + row * GSP + q * 8) =
                    *reinterpret_cast<const uint4*>(Ag + (size_t)row * lda + kc * 32 + q * 8);
                *reinterpret_cast<uint4*>(sB + row * GSP + q * 8) =
                    *reinterpret_cast<const uint4*>(Bg + (size_t)row * K + kc * 32 + q * 8);
            }
            __syncthreads();

            uint32_t bfr[4][4];
            #pragma unroll
            for (int j = 0; j < 4; j++)
                ldm_x4(bfr[j], smem_u32(sB + (b_row + j * 8) * GSP + b_col));

            #pragma unroll
            for (int h = 0; h < 2; h++) {
                #pragma unroll
                for (int i = 0; i < 2; i++) {
                    uint32_t afr[4];
                    ldm_x4(afr, smem_u32(sA + (a_row + i * 16) * GSP + h * 16 + a_col));
                    #pragma unroll
                    for (int j = 0; j < 4; j++)
                        mma_bf16(acc[i][j], afr, bfr[j][2 * h], bfr[j][2 * h + 1]);
                }
            }
        }
    }

    const int er = lane >> 2, ec = (lane & 3) * 2;
    #pragma unroll
    for (int i = 0; i < 2; i++) {
        #pragma unroll
        for (int j = 0; j < 4; j++) {
            int gc = col0 + wn * 32 + j * 8 + ec;
            #pragma unroll
            for (int rr = 0; rr < 2; rr++) {
                int row = row0 + wm * 32 + i * 16 + er + rr * 8;
                if (row >= M) continue;
                float v0 = acc[i][j][2 * rr + 0];
                float v1 = acc[i][j][2 * rr + 1];
                if (EPI == 0) {
                    *reinterpret_cast<float2*>(C + (size_t)row * ldc + gc) =
                        make_float2(v0, v1);
                } else if (EPI == 1) {
                    v0 = fmaxf(v0 + bias[gc] + add1[(size_t)row * DH + gc]
                                  + add2[(size_t)row * DH + gc], 0.f);
                    v1 = fmaxf(v1 + bias[gc + 1] + add1[(size_t)row * DH + gc + 1]
                                  + add2[(size_t)row * DH + gc + 1], 0.f);
                    __nv_bfloat16 h0 = __float2bfloat16(v0);
                    __nv_bfloat16 h1 = __float2bfloat16(v1);
                    __nv_bfloat16 l0 = __float2bfloat16(v0 - __bfloat162float(h0));
                    __nv_bfloat16 l1 = __float2bfloat16(v1 - __bfloat162float(h1));
                    __nv_bfloat162 hv; hv.x = h0; hv.y = h1;
                    __nv_bfloat162 lv; lv.x = l0; lv.y = l1;
                    *reinterpret_cast<__nv_bfloat162*>(Oh + (size_t)row * ldc + gc) = hv;
                    *reinterpret_cast<__nv_bfloat162*>(Ol + (size_t)row * ldc + gc) = lv;
                } else {  // EPI == 3
                    *reinterpret_cast<float2*>(C + (size_t)row * ldc + gc) =
                        make_float2(v0 + bias[gc], v1 + bias[gc + 1]);
                }
            }
        }
    }
}

// ---------------- tensor-core match GEMM (split-2 bf16) ----------------
#define SPAD 40

__global__ void __launch_bounds__(256, 2) match_mma_kernel(
    const __nv_bfloat16* __restrict__ Ah, const __nv_bfloat16* __restrict__ Al,
    const __nv_bfloat16* __restrict__ Bh, const __nv_bfloat16* __restrict__ Bl,
    float* __restrict__ Eout)
{
    __shared__ __nv_bfloat16 sA[128 * SPAD];
    __shared__ __nv_bfloat16 sB[128 * SPAD];
    const int tid = threadIdx.x;
    const int wid = tid >> 5, lane = tid & 31;
    const int wm = wid & 3, wn = wid >> 2;
    const int row0 = blockIdx.y * 128, col0 = blockIdx.x * 128;

    float acc[2][8][4];
    #pragma unroll
    for (int i = 0; i < 2; i++)
        #pragma unroll
        for (int j = 0; j < 8; j++)
            #pragma unroll
            for (int q = 0; q < 4; q++) acc[i][j][q] = 0.f;

    const int a_row = wm * 32 + (lane < 16 ? lane : lane - 16);
    const int a_col = (lane < 16 ? 0 : 8);
    const int b_row = wn * 64 + (lane & 7);
    const int b_col = (lane >> 3) * 8;

    #pragma unroll
    for (int p = 0; p < 3; p++) {
        const __nv_bfloat16* Ag = (p == 2 ? Al : Ah) + (size_t)row0 * DH;
        const __nv_bfloat16* Bg = (p == 1 ? Bl : Bh) + (size_t)col0 * DH;
        for (int kc = 0; kc < DH / 32; kc++) {
            __syncthreads();
            #pragma unroll
            for (int r = 0; r < 2; r++) {
                int idx = tid * 2 + r;
                int row = idx >> 2, q = idx & 3;
                *reinterpret_cast<uint4*>(sA + row * SPAD + q * 8) =
                    *reinterpret_cast<const uint4*>(Ag + (size_t)row * DH + kc * 32 + q * 8);
                *reinterpret_cast<uint4*>(sB + row * SPAD + q * 8) =
                    *reinterpret_cast<const uint4*>(Bg + (size_t)row * DH + kc * 32 + q * 8);
            }
            __syncthreads();

            uint32_t bfr[8][4];
            #pragma unroll
            for (int j = 0; j < 8; j++)
                ldm_x4(bfr[j], smem_u32(sB + (b_row + j * 8) * SPAD + b_col));

            #pragma unroll
            for (int h = 0; h < 2; h++) {
                #pragma unroll
                for (int i = 0; i < 2; i++) {
                    uint32_t afr[4];
                    ldm_x4(afr, smem_u32(sA + (a_row + i * 16) * SPAD + h * 16 + a_col));
                    #pragma unroll
                    for (int j = 0; j < 8; j++)
                        mma_bf16(acc[i][j], afr, bfr[j][2 * h], bfr[j][2 * h + 1]);
                }
            }
        }
    }

    const int er = lane >> 2, ec = (lane & 3) * 2;
    #pragma unroll
    for (int i = 0; i < 2; i++) {
        int gr0 = row0 + wm * 32 + i * 16 + er;
        #pragma unroll
        for (int j = 0; j < 8; j++) {
            int gc = col0 + wn * 64 + j * 8 + ec;
            float2 o0, o1;
            o0.x = __expf(20.f * (acc[i][j][0] + 1e-10f));
            o0.y = __expf(20.f * (acc[i][j][1] + 1e-10f));
            o1.x = __expf(20.f * (acc[i][j][2] + 1e-10f));
            o1.y = __expf(20.f * (acc[i][j][3] + 1e-10f));
            *reinterpret_cast<float2*>(Eout + (size_t)gr0 * NMAX + gc) = o0;
            *reinterpret_cast<float2*>(Eout + (size_t)(gr0 + 8) * NMAX + gc) = o1;
        }
    }
}

// ---------------- fused row L2 normalize + bf16 split ----------------
__global__ void l2split_k(const float* __restrict__ H, __nv_bfloat16* __restrict__ sh,
                          __nv_bfloat16* __restrict__ sl)
{
    int row = blockIdx.x;
    int tid = threadIdx.x;
    float v = H[(size_t)row * DH + tid];
    __shared__ float red[256];
    red[tid] = v * v;
    __syncthreads();
    for (int s = 128; s > 0; s >>= 1) {
        if (tid < s) red[tid] += red[tid + s];
        __syncthreads();
    }
    float sc = 1.0f / fmaxf(sqrtf(red[0]), 1e-12f);
    float nv = v * sc;
    __nv_bfloat16 h = __float2bfloat16(nv);
    float r = nv - __bfloat162float(h);
    sh[(size_t)row * DH + tid] = h;
    sl[(size_t)row * DH + tid] = __float2bfloat16(r);
}

// ---------------- sinkhorn factor passes ----------------
__global__ void colsum_k(const float* __restrict__ Eb, const float* __restrict__ r,
                         float* __restrict__ cs)
{
    int j = blockIdx.x * 256 + threadIdx.x;
    int i0 = blockIdx.y * 128;
    float acc = 0.f;
    #pragma unroll 4
    for (int i = 0; i < 128; i++)
        acc += Eb[(size_t)(i0 + i) * NMAX + j] * __ldg(&r[i0 + i]);
    atomicAdd(&cs[j], acc);
}

__global__ void rowsum_k(const float* __restrict__ Eb, const float* __restrict__ c,
                         float* __restrict__ r)
{
    int i = blockIdx.x, tid = threadIdx.x;
    const float4* row = reinterpret_cast<const float4*>(Eb + (size_t)i * NMAX);
    const float4* c4 = reinterpret_cast<const float4*>(c);
    float acc = 0.f;
    for (int j = tid; j < NMAX / 4; j += 256) {
        float4 e = row[j], cv = c4[j];
        acc += e.x * cv.x + e.y * cv.y + e.z * cv.z + e.w * cv.w;
    }
    __shared__ float red[256];
    red[tid] = acc;
    __syncthreads();
    for (int s = 128; s > 0; s >>= 1) {
        if (tid < s) red[tid] += red[tid + s];
        __syncthreads();
    }
    if (tid == 0) r[i] = 1.0f / red[0];
}

__global__ void finalize_k(const float* __restrict__ Eb, const float* __restrict__ r,
                           const float* __restrict__ c, float* __restrict__ out, int rows)
{
    int t = blockIdx.x * blockDim.x + threadIdx.x;
    if (t >= rows * (NMAX / 4)) return;
    int i = t >> 10, j = t & 1023;
    float ri = r[i];
    float4 e = reinterpret_cast<const float4*>(Eb)[(size_t)i * (NMAX / 4) + j];
    float4 cv = reinterpret_cast<const float4*>(c)[j];
    float4 o;
    o.x = e.x * ri * cv.x; o.y = e.y * ri * cv.y;
    o.z = e.z * ri * cv.z; o.w = e.w * ri * cv.w;
    reinterpret_cast<float4*>(out)[t] = o;
}

// ---------------- host driver ----------------
static inline int cdiv(int a, int b) { return (a + b - 1) / b; }

extern "C" void kernel_launch(void* const* d_in, const int* in_sizes, int n_in,
                              void* d_out, int out_size)
{
    const float* x_s = (const float*)d_in[0];
    const float* x_t = (const float*)d_in[1];
    const int* edges = (const int*)d_in[2];
    const int* edget = (const int*)d_in[3];
    const float* W1[3], *W2[3], *Wr[3], *br[3];
    for (int l = 0; l < 3; l++) {
        W1[l] = (const float*)d_in[4 + 4 * l];
        W2[l] = (const float*)d_in[5 + 4 * l];
        Wr[l] = (const float*)d_in[6 + 4 * l];
        br[l] = (const float*)d_in[7 + 4 * l];
    }
    const float* final_w = (const float*)d_in[16];
    const float* final_b = (const float*)d_in[17];

    const int NS = in_sizes[0] / 128;
    const int NT = in_sizes[1] / 128;
    const int ES = in_sizes[2] / 2;
    const int ET = in_sizes[3] / 2;

    float *tmp1, *tmp2, *agg1, *agg2, *Hf, *Eb, *rr, *cc, *csum, *inv_a, *inv_b;
    int *cnt_a, *cnt_b, *off_a, *off_b, *cur_a, *cur_b, *lst_a, *lst_b;
    __nv_bfloat16 *Xh, *Xl, *Wth, *Wtl, *sh, *sl;
    cudaGetSymbolAddress((void**)&Xh, g_Xh);
    cudaGetSymbolAddress((void**)&Xl, g_Xl);
    cudaGetSymbolAddress((void**)&Wth, g_Wth);
    cudaGetSymbolAddress((void**)&Wtl, g_Wtl);
    cudaGetSymbolAddress((void**)&tmp1, g_tmp1);
    cudaGetSymbolAddress((void**)&tmp2, g_tmp2);
    cudaGetSymbolAddress((void**)&agg1, g_agg1);
    cudaGetSymbolAddress((void**)&agg2, g_agg2);
    cudaGetSymbolAddress((void**)&Hf, g_H);
    cudaGetSymbolAddress((void**)&Eb, g_E);
    cudaGetSymbolAddress((void**)&rr, g_r);
    cudaGetSymbolAddress((void**)&cc, g_c);
    cudaGetSymbolAddress((void**)&csum, g_colsum);
    cudaGetSymbolAddress((void**)&cnt_a, g_cnt_a);
    cudaGetSymbolAddress((void**)&cnt_b, g_cnt_b);
    cudaGetSymbolAddress((void**)&inv_a, g_inv_a);
    cudaGetSymbolAddress((void**)&inv_b, g_inv_b);
    cudaGetSymbolAddress((void**)&off_a, g_off_a);
    cudaGetSymbolAddress((void**)&off_b, g_off_b);
    cudaGetSymbolAddress((void**)&cur_a, g_cur_a);
    cudaGetSymbolAddress((void**)&cur_b, g_cur_b);
    cudaGetSymbolAddress((void**)&lst_a, g_lst_a);
    cudaGetSymbolAddress((void**)&lst_b, g_lst_b);
    cudaGetSymbolAddress((void**)&sh, g_sh);
    cudaGetSymbolAddress((void**)&sl, g_sl);

    // ---- transpose+split all weights ----
    int woff[10];
    {
        int o = 0, fan = 128;
        for (int l = 0; l < 3; l++) {
            for (int w = 0; w < 3; w++) { woff[l * 3 + w] = o; o += fan * DH; }
            fan = DH;
        }
        woff[9] = o;  // final_w: 896*256
    }
    for (int l = 0; l < 3; l++) {
        int fan = (l == 0) ? 128 : DH;
        const float* ws[3] = { W1[l], W2[l], Wr[l] };
        for (int w = 0; w < 3; w++)
            wtsplit_k<<<cdiv(fan * DH, 256), 256>>>(ws[w], Wth + woff[l * 3 + w],
                                                    Wtl + woff[l * 3 + w], fan, DH);
    }
    wtsplit_k<<<cdiv(DCAT * DH, 256), 256>>>(final_w, Wth + woff[9], Wtl + woff[9],
                                             DCAT, DH);

    for (int gi = 0; gi < 2; gi++) {
        const float* x = gi == 0 ? x_s : x_t;
        const int* ep = gi == 0 ? edges : edget;
        int N = gi == 0 ? NS : NT;
        int E = gi == 0 ? ES : ET;
        const int* src = ep;
        const int* dst = ep + E;
        __nv_bfloat16* Xgh = Xh + (size_t)gi * NMAX * DCAT;
        __nv_bfloat16* Xgl = Xl + (size_t)gi * NMAX * DCAT;

        copyx_split<<<cdiv(N * 128, 256), 256>>>(x, Xgh, Xgl, N);

        // ---- CSR build: dir A (group by dst, list src), dir B (by src, list dst)
        fill_i<<<cdiv(NMAX, 256), 256>>>(cnt_a, 0, NMAX);
        fill_i<<<cdiv(NMAX, 256), 256>>>(cnt_b, 0, NMAX);
        count_k<<<cdiv(E, 256), 256>>>(dst, cnt_a, E);
        count_k<<<cdiv(E, 256), 256>>>(src, cnt_b, E);
        inv_k<<<cdiv(NMAX, 256), 256>>>(cnt_a, inv_a, NMAX);
        inv_k<<<cdiv(NMAX, 256), 256>>>(cnt_b, inv_b, NMAX);
        scan_k<<<1, 1024>>>(cnt_a, off_a, cur_a);
        scan_k<<<1, 1024>>>(cnt_b, off_b, cur_b);
        place_k<<<cdiv(E, 256), 256>>>(dst, src, cur_a, lst_a, E);
        place_k<<<cdiv(E, 256), 256>>>(src, dst, cur_b, lst_b, E);

        int off = 0, fan = 128;
        for (int l = 0; l < 3; l++) {
            const __nv_bfloat16* Ahp = Xgh + off;
            const __nv_bfloat16* Alp = Xgl + off;
            dim3 grid(DH / 64, cdiv(N, 64));
            gemm_mma<0><<<grid, 128>>>(Ahp, Alp, DCAT,
                                       Wth + woff[l * 3 + 0], Wtl + woff[l * 3 + 0],
                                       tmp1, DH, N, fan, nullptr, nullptr, nullptr,
                                       nullptr, nullptr);
            gemm_mma<0><<<grid, 128>>>(Ahp, Alp, DCAT,
                                       Wth + woff[l * 3 + 1], Wtl + woff[l * 3 + 1],
                                       tmp2, DH, N, fan, nullptr, nullptr, nullptr,
                                       nullptr, nullptr);
            gather_k<<<N, 256>>>(tmp1, off_a, cnt_a, inv_a, lst_a, agg1);
            gather_k<<<N, 256>>>(tmp2, off_b, cnt_b, inv_b, lst_b, agg2);
            int noff = off + fan;   // 0->128, 128->384, 384->640
            gemm_mma<1><<<grid, 128>>>(Ahp, Alp, DCAT,
                                       Wth + woff[l * 3 + 2], Wtl + woff[l * 3 + 2],
                                       nullptr, DCAT, N, fan, br[l], agg1, agg2,
                                       Xgh + noff, Xgl + noff);
            off = noff;
            fan = DH;
        }
        // final linear: H = Xcat @ final_w + final_b (K = 896)
        dim3 gridf(DH / 64, cdiv(N, 64));
        gemm_mma<3><<<gridf, 128>>>(Xgh, Xgl, DCAT, Wth + woff[9], Wtl + woff[9],
                                    Hf, DH, N, DCAT, final_b, nullptr, nullptr,
                                    nullptr, nullptr);
        l2split_k<<<N, 256>>>(Hf, sh + (size_t)gi * NMAX * DH,
                              sl + (size_t)gi * NMAX * DH);
    }

    // match -> E = exp(20*(Hs_n @ Ht_n^T + 1e-10)) via mma.sync bf16 split-2
    {
        dim3 gm(NMAX / 128, NMAX / 128);
        match_mma_kernel<<<gm, 256>>>(sh, sl,
                                      sh + (size_t)NMAX * DH, sl + (size_t)NMAX * DH, Eb);
        // dummy rows: exp(20*(eps+eps)) == 1.0f in fp32
        fill_f<<<cdiv((NMAX - NS) * NMAX, 256), 256>>>(Eb + (size_t)NS * NMAX, 1.0f,
                                                       (NMAX - NS) * NMAX);
    }

    // sinkhorn via row/col scale factors: 5x (col-norm, row-norm)
    fill_f<<<cdiv(NMAX, 256), 256>>>(rr, 1.0f, NMAX);
    for (int it = 0; it < 5; it++) {
        fill_f<<<cdiv(NMAX, 256), 256>>>(csum, 0.f, NMAX);
        colsum_k<<<dim3(NMAX / 256, 32), 256>>>(Eb, rr, csum);
        recip_k<<<cdiv(NMAX, 256), 256>>>(csum, cc, NMAX);
        rowsum_k<<<NMAX, 256>>>(Eb, cc, rr);
    }
    finalize_k<<<cdiv(NS * (NMAX / 4), 256), 256>>>(Eb, rr, cc, (float*)d_out, NS);
}

// round 6
// speedup vs baseline: 2.0884x; 1.3494x over previous
#include <cuda_runtime.h>
#include <cuda_bf16.h>
#include <math.h>
#include <stdint.h>

#define NMAX 4096
#define DH   256
#define DCAT 896
#define EMAX 65536
#define WTOT 720896   // total transposed-weight elems

// ---------------- scratch (device globals; no runtime alloc) ----------------
__device__ __align__(16) __nv_bfloat16 g_Xh[2][(size_t)NMAX * DCAT];
__device__ __align__(16) __nv_bfloat16 g_Xl[2][(size_t)NMAX * DCAT];
__device__ __align__(16) __nv_bfloat16 g_Wth[WTOT];
__device__ __align__(16) __nv_bfloat16 g_Wtl[WTOT];
__device__ __align__(16) float g_tmp12[(size_t)NMAX * 512];
__device__ __align__(16) float g_agg1[(size_t)NMAX * DH];
__device__ __align__(16) float g_agg2[(size_t)NMAX * DH];
__device__ __align__(16) float g_H[(size_t)NMAX * DH];
__device__ __align__(16) float g_E[(size_t)NMAX * NMAX];   // exp(20*(match+eps)), 64MB
__device__ __align__(16) float g_r[NMAX];
__device__ __align__(16) float g_c[NMAX];
__device__ __align__(16) float g_colsum[NMAX];
__device__ __align__(16) int   g_cnt_a[NMAX];
__device__ __align__(16) int   g_cnt_b[NMAX];
__device__ __align__(16) float g_inv_a[NMAX];
__device__ __align__(16) float g_inv_b[NMAX];
__device__ __align__(16) int g_off_a[NMAX];
__device__ __align__(16) int g_off_b[NMAX];
__device__ __align__(16) int g_cur_a[NMAX];
__device__ __align__(16) int g_cur_b[NMAX];
__device__ __align__(16) int g_lst_a[EMAX];
__device__ __align__(16) int g_lst_b[EMAX];
__device__ __align__(16) __nv_bfloat16 g_sh[2][(size_t)NMAX * DH];
__device__ __align__(16) __nv_bfloat16 g_sl[2][(size_t)NMAX * DH];

// ---------------- PTX helpers ----------------
__device__ __forceinline__ uint32_t smem_u32(const void* p) {
    uint32_t a;
    asm("{ .reg .u64 t; cvta.to.shared.u64 t, %1; cvt.u32.u64 %0, t; }" : "=r"(a) : "l"(p));
    return a;
}
#define CP_ASYNC16(saddr, gptr) \
    asm volatile("cp.async.cg.shared.global [%0], [%1], 16;" :: "r"(saddr), "l"(gptr))
#define CP_COMMIT() asm volatile("cp.async.commit_group;" ::: "memory")
#define CP_WAIT1()  asm volatile("cp.async.wait_group 1;" ::: "memory")

__device__ __forceinline__ void ldm_x4(uint32_t* r, uint32_t addr) {
    asm volatile("ldmatrix.sync.aligned.m8n8.x4.shared.b16 {%0,%1,%2,%3}, [%4];"
        : "=r"(r[0]), "=r"(r[1]), "=r"(r[2]), "=r"(r[3]) : "r"(addr));
}
__device__ __forceinline__ void mma_bf16(float* d, const uint32_t* a, uint32_t b0, uint32_t b1) {
    asm volatile(
        "mma.sync.aligned.m16n8k16.row.col.f32.bf16.bf16.f32 "
        "{%0,%1,%2,%3}, {%4,%5,%6,%7}, {%8,%9}, {%0,%1,%2,%3};"
        : "+f"(d[0]), "+f"(d[1]), "+f"(d[2]), "+f"(d[3])
        : "r"(a[0]), "r"(a[1]), "r"(a[2]), "r"(a[3]), "r"(b0), "r"(b1));
}

// ---------------- small utility kernels ----------------
__global__ void fill_f(float* p, float v, int n) {
    int t = blockIdx.x * blockDim.x + threadIdx.x;
    if (t < n) p[t] = v;
}
__global__ void fill_i2(int* a, int* b, int n) {
    int t = blockIdx.x * blockDim.x + threadIdx.x;
    if (t < n) { a[t] = 0; b[t] = 0; }
}
__global__ void count2_k(const int* __restrict__ dst, const int* __restrict__ src,
                         int* __restrict__ ca, int* __restrict__ cb, int E)
{
    int t = blockIdx.x * blockDim.x + threadIdx.x;
    if (t < E) { atomicAdd(&ca[dst[t]], 1); atomicAdd(&cb[src[t]], 1); }
}
__global__ void inv2_k(const int* __restrict__ ca, const int* __restrict__ cb,
                       float* __restrict__ ia, float* __restrict__ ib, int n)
{
    int t = blockIdx.x * blockDim.x + threadIdx.x;
    if (t < n) {
        ia[t] = 1.0f / (float)max(ca[t], 1);
        ib[t] = 1.0f / (float)max(cb[t], 1);
    }
}
__global__ void recip_k(const float* __restrict__ a, float* __restrict__ b, int n) {
    int t = blockIdx.x * blockDim.x + threadIdx.x;
    if (t < n) b[t] = 1.0f / a[t];
}

// exclusive scan (grid=2: blk0 -> dir A, blk1 -> dir B)
__global__ void scan2_k(const int* __restrict__ ca, const int* __restrict__ cb,
                        int* __restrict__ oa, int* __restrict__ ob,
                        int* __restrict__ ra, int* __restrict__ rb)
{
    __shared__ int s[NMAX];
    const int* cnt = blockIdx.x == 0 ? ca : cb;
    int* off = blockIdx.x == 0 ? oa : ob;
    int* cur = blockIdx.x == 0 ? ra : rb;
    int tid = threadIdx.x;
    #pragma unroll
    for (int j = 0; j < 4; j++) s[tid + j * 1024] = cnt[tid + j * 1024];
    __syncthreads();
    for (int d = 1; d < NMAX; d <<= 1) {
        int v[4];
        #pragma unroll
        for (int j = 0; j < 4; j++) {
            int i = tid + j * 1024;
            v[j] = (i >= d) ? s[i - d] : 0;
        }
        __syncthreads();
        #pragma unroll
        for (int j = 0; j < 4; j++) s[tid + j * 1024] += v[j];
        __syncthreads();
    }
    #pragma unroll
    for (int j = 0; j < 4; j++) {
        int i = tid + j * 1024;
        int o = s[i] - cnt[i];
        off[i] = o;
        cur[i] = o;
    }
}

__global__ void place2_k(const int* __restrict__ dst, const int* __restrict__ src,
                         int* __restrict__ ca, int* __restrict__ cb,
                         int* __restrict__ la, int* __restrict__ lb, int E)
{
    int t = blockIdx.x * blockDim.x + threadIdx.x;
    if (t >= E) return;
    int d = dst[t], s = src[t];
    la[atomicAdd(&ca[d], 1)] = s;
    lb[atomicAdd(&cb[s], 1)] = d;
}

// CSR gather-mean: out[n][tid] = inv[n] * sum_{e in list(n)} vals[lst[e]][tid]
__global__ void __launch_bounds__(256) gather_k(
    const float* __restrict__ vals, int ldv, const int* __restrict__ off,
    const int* __restrict__ cnt, const float* __restrict__ inv,
    const int* __restrict__ lst, float* __restrict__ out)
{
    __shared__ int sl[64];
    const int n = blockIdx.x;
    const int tid = threadIdx.x;
    const int beg = off[n];
    const int d = cnt[n];
    float acc = 0.f;
    for (int base = 0; base < d; base += 64) {
        int chunk = min(64, d - base);
        if (tid < chunk) sl[tid] = lst[beg + base + tid];
        __syncthreads();
        int e = 0;
        for (; e + 4 <= chunk; e += 4) {
            int s0 = sl[e], s1 = sl[e + 1], s2 = sl[e + 2], s3 = sl[e + 3];
            float v0 = vals[(size_t)s0 * ldv + tid];
            float v1 = vals[(size_t)s1 * ldv + tid];
            float v2 = vals[(size_t)s2 * ldv + tid];
            float v3 = vals[(size_t)s3 * ldv + tid];
            acc += (v0 + v1) + (v2 + v3);
        }
        for (; e < chunk; e++)
            acc += vals[(size_t)sl[e] * ldv + tid];
        __syncthreads();
    }
    out[(size_t)n * DH + tid] = acc * inv[n];
}

// input features -> bf16 hi/lo into Xsplit cols 0..127
__global__ void copyx_split(const float* __restrict__ x, __nv_bfloat16* __restrict__ Xh,
                            __nv_bfloat16* __restrict__ Xl, int N)
{
    int t = blockIdx.x * blockDim.x + threadIdx.x;
    if (t >= N * 128) return;
    int row = t >> 7, c = t & 127;
    float v = x[t];
    __nv_bfloat16 h = __float2bfloat16(v);
    float r = v - __bfloat162float(h);
    Xh[(size_t)row * DCAT + c] = h;
    Xl[(size_t)row * DCAT + c] = __float2bfloat16(r);
}
// transpose W [K][N] -> [N][K] bf16 hi/lo
__global__ void wtsplit_k(const float* __restrict__ W, __nv_bfloat16* __restrict__ th,
                          __nv_bfloat16* __restrict__ tl, int K, int N)
{
    int t = blockIdx.x * blockDim.x + threadIdx.x;
    if (t >= K * N) return;
    int k = t / N, n = t % N;
    float v = W[t];
    __nv_bfloat16 h = __float2bfloat16(v);
    float r = v - __bfloat162float(h);
    th[(size_t)n * K + k] = h;
    tl[(size_t)n * K + k] = __float2bfloat16(r);
}

// ---------------- fused GNN GEMM: single k-loop, cp.async 2-stage ----------
// C[m][n] = sum_k A[m][k]*Bt[n][k], split-2: AhBh + AhBl + AlBh, fp32 accum.
// CTA 64x64, 128 thr (2m x 2n warps), warp 32x32 = 2x4 m16n8k16.
#define GSP 40

template <int EPI>
__global__ void __launch_bounds__(128) gemm_f(
    const __nv_bfloat16* __restrict__ Ah, const __nv_bfloat16* __restrict__ Al, int lda,
    const __nv_bfloat16* __restrict__ Bh, const __nv_bfloat16* __restrict__ Bl,
    float* __restrict__ C, int ldc, int M, int K,
    const float* __restrict__ bias, const float* __restrict__ add1,
    const float* __restrict__ add2,
    __nv_bfloat16* __restrict__ Oh, __nv_bfloat16* __restrict__ Ol)
{
    __shared__ __nv_bfloat16 s[2][4][64 * GSP];   // [stage][Ah,Al,Bh,Bl]
    const int tid = threadIdx.x;
    const int lane = tid & 31, wid = tid >> 5;
    const int wm = wid & 1, wn = wid >> 1;
    const int row0 = blockIdx.y * 64, col0 = blockIdx.x * 64;
    const int nk = K / 32;

    const __nv_bfloat16* base[4] = {
        Ah + (size_t)row0 * lda, Al + (size_t)row0 * lda,
        Bh + (size_t)col0 * K, Bl + (size_t)col0 * K };
    const int ld4[4] = { lda, lda, K, K };

    const int l_row = tid >> 1;          // 0..63
    const int l_q0 = (tid & 1) * 2;      // 0 or 2

    auto load_stage = [&](int kc, int st) {
        #pragma unroll
        for (int t4 = 0; t4 < 4; t4++) {
            const __nv_bfloat16* g = base[t4] + (size_t)l_row * ld4[t4] + kc * 32;
            uint32_t sa = smem_u32(&s[st][t4][l_row * GSP]);
            CP_ASYNC16(sa + (l_q0 + 0) * 16, g + (l_q0 + 0) * 8);
            CP_ASYNC16(sa + (l_q0 + 1) * 16, g + (l_q0 + 1) * 8);
        }
    };

    float acc[2][4][4];
    #pragma unroll
    for (int i = 0; i < 2; i++)
        #pragma unroll
        for (int j = 0; j < 4; j++)
            #pragma unroll
            for (int q = 0; q < 4; q++) acc[i][j][q] = 0.f;

    const int a_row = wm * 32 + (lane < 16 ? lane : lane - 16);
    const int a_col = (lane < 16 ? 0 : 8);
    const int b_row = wn * 32 + (lane & 7);
    const int b_col = (lane >> 3) * 8;

    load_stage(0, 0);
    CP_COMMIT();

    for (int kc = 0; kc < nk; kc++) {
        if (kc + 1 < nk) load_stage(kc + 1, (kc + 1) & 1);
        CP_COMMIT();
        CP_WAIT1();
        __syncthreads();
        const int st = kc & 1;

        uint32_t bh[4][4], bl[4][4];
        #pragma unroll
        for (int j = 0; j < 4; j++) {
            ldm_x4(bh[j], smem_u32(&s[st][2][(b_row + j * 8) * GSP + b_col]));
            ldm_x4(bl[j], smem_u32(&s[st][3][(b_row + j * 8) * GSP + b_col]));
        }
        #pragma unroll
        for (int h = 0; h < 2; h++) {
            #pragma unroll
            for (int i = 0; i < 2; i++) {
                uint32_t ah[4], al[4];
                ldm_x4(ah, smem_u32(&s[st][0][(a_row + i * 16) * GSP + h * 16 + a_col]));
                ldm_x4(al, smem_u32(&s[st][1][(a_row + i * 16) * GSP + h * 16 + a_col]));
                #pragma unroll
                for (int j = 0; j < 4; j++) {
                    mma_bf16(acc[i][j], ah, bh[j][2 * h], bh[j][2 * h + 1]);
                    mma_bf16(acc[i][j], ah, bl[j][2 * h], bl[j][2 * h + 1]);
                    mma_bf16(acc[i][j], al, bh[j][2 * h], bh[j][2 * h + 1]);
                }
            }
        }
        __syncthreads();
    }

    const int er = lane >> 2, ec = (lane & 3) * 2;
    #pragma unroll
    for (int i = 0; i < 2; i++) {
        #pragma unroll
        for (int j = 0; j < 4; j++) {
            int gc = col0 + wn * 32 + j * 8 + ec;
            #pragma unroll
            for (int rr = 0; rr < 2; rr++) {
                int row = row0 + wm * 32 + i * 16 + er + rr * 8;
                if (row >= M) continue;
                float v0 = acc[i][j][2 * rr + 0];
                float v1 = acc[i][j][2 * rr + 1];
                if (EPI == 0) {
                    *reinterpret_cast<float2*>(C + (size_t)row * ldc + gc) =
                        make_float2(v0, v1);
                } else if (EPI == 1) {
                    v0 = fmaxf(v0 + bias[gc] + add1[(size_t)row * DH + gc]
                                  + add2[(size_t)row * DH + gc], 0.f);
                    v1 = fmaxf(v1 + bias[gc + 1] + add1[(size_t)row * DH + gc + 1]
                                  + add2[(size_t)row * DH + gc + 1], 0.f);
                    __nv_bfloat16 h0 = __float2bfloat16(v0);
                    __nv_bfloat16 h1 = __float2bfloat16(v1);
                    __nv_bfloat16 l0 = __float2bfloat16(v0 - __bfloat162float(h0));
                    __nv_bfloat16 l1 = __float2bfloat16(v1 - __bfloat162float(h1));
                    __nv_bfloat162 hv; hv.x = h0; hv.y = h1;
                    __nv_bfloat162 lv; lv.x = l0; lv.y = l1;
                    *reinterpret_cast<__nv_bfloat162*>(Oh + (size_t)row * ldc + gc) = hv;
                    *reinterpret_cast<__nv_bfloat162*>(Ol + (size_t)row * ldc + gc) = lv;
                } else {  // EPI == 3
                    *reinterpret_cast<float2*>(C + (size_t)row * ldc + gc) =
                        make_float2(v0 + bias[gc], v1 + bias[gc + 1]);
                }
            }
        }
    }
}

// ---------------- match GEMM: 3-pass, cp.async 2-stage over flat (p,kc) -----
#define SPAD 40

__global__ void __launch_bounds__(256, 2) match_mma_kernel(
    const __nv_bfloat16* __restrict__ Ah, const __nv_bfloat16* __restrict__ Al,
    const __nv_bfloat16* __restrict__ Bh, const __nv_bfloat16* __restrict__ Bl,
    float* __restrict__ Eout)
{
    __shared__ __nv_bfloat16 s[2][2][128 * SPAD];   // [stage][A,B]
    const int tid = threadIdx.x;
    const int wid = tid >> 5, lane = tid & 31;
    const int wm = wid & 3, wn = wid >> 2;
    const int row0 = blockIdx.y * 128, col0 = blockIdx.x * 128;

    const __nv_bfloat16* Asrc[3] = {
        Ah + (size_t)row0 * DH, Ah + (size_t)row0 * DH, Al + (size_t)row0 * DH };
    const __nv_bfloat16* Bsrc[3] = {
        Bh + (size_t)col0 * DH, Bl + (size_t)col0 * DH, Bh + (size_t)col0 * DH };

    const int l_row = tid >> 1;          // 0..127
    const int l_q0 = (tid & 1) * 2;

    auto load_stage = [&](int it, int st) {
        int p = it >> 3, kc = it & 7;
        const __nv_bfloat16* ga = Asrc[p] + (size_t)l_row * DH + kc * 32;
        const __nv_bfloat16* gb = Bsrc[p] + (size_t)l_row * DH + kc * 32;
        uint32_t sa = smem_u32(&s[st][0][l_row * SPAD]);
        uint32_t sb = smem_u32(&s[st][1][l_row * SPAD]);
        CP_ASYNC16(sa + (l_q0 + 0) * 16, ga + (l_q0 + 0) * 8);
        CP_ASYNC16(sa + (l_q0 + 1) * 16, ga + (l_q0 + 1) * 8);
        CP_ASYNC16(sb + (l_q0 + 0) * 16, gb + (l_q0 + 0) * 8);
        CP_ASYNC16(sb + (l_q0 + 1) * 16, gb + (l_q0 + 1) * 8);
    };

    float acc[2][8][4];
    #pragma unroll
    for (int i = 0; i < 2; i++)
        #pragma unroll
        for (int j = 0; j < 8; j++)
            #pragma unroll
            for (int q = 0; q < 4; q++) acc[i][j][q] = 0.f;

    const int a_row = wm * 32 + (lane < 16 ? lane : lane - 16);
    const int a_col = (lane < 16 ? 0 : 8);
    const int b_row = wn * 64 + (lane & 7);
    const int b_col = (lane >> 3) * 8;

    load_stage(0, 0);
    CP_COMMIT();

    for (int it = 0; it < 24; it++) {
        if (it + 1 < 24) load_stage(it + 1, (it + 1) & 1);
        CP_COMMIT();
        CP_WAIT1();
        __syncthreads();
        const int st = it & 1;

        uint32_t bfr[8][4];
        #pragma unroll
        for (int j = 0; j < 8; j++)
            ldm_x4(bfr[j], smem_u32(&s[st][1][(b_row + j * 8) * SPAD + b_col]));

        #pragma unroll
        for (int h = 0; h < 2; h++) {
            #pragma unroll
            for (int i = 0; i < 2; i++) {
                uint32_t afr[4];
                ldm_x4(afr, smem_u32(&s[st][0][(a_row + i * 16) * SPAD + h * 16 + a_col]));
                #pragma unroll
                for (int j = 0; j < 8; j++)
                    mma_bf16(acc[i][j], afr, bfr[j][2 * h], bfr[j][2 * h + 1]);
            }
        }
        __syncthreads();
    }

    const int er = lane >> 2, ec = (lane & 3) * 2;
    #pragma unroll
    for (int i = 0; i < 2; i++) {
        int gr0 = row0 + wm * 32 + i * 16 + er;
        #pragma unroll
        for (int j = 0; j < 8; j++) {
            int gc = col0 + wn * 64 + j * 8 + ec;
            float2 o0, o1;
            o0.x = __expf(20.f * (acc[i][j][0] + 1e-10f));
            o0.y = __expf(20.f * (acc[i][j][1] + 1e-10f));
            o1.x = __expf(20.f * (acc[i][j][2] + 1e-10f));
            o1.y = __expf(20.f * (acc[i][j][3] + 1e-10f));
            *reinterpret_cast<float2*>(Eout + (size_t)gr0 * NMAX + gc) = o0;
            *reinterpret_cast<float2*>(Eout + (size_t)(gr0 + 8) * NMAX + gc) = o1;
        }
    }
}

// ---------------- fused row L2 normalize + bf16 split ----------------
__global__ void l2split_k(const float* __restrict__ H, __nv_bfloat16* __restrict__ sh,
                          __nv_bfloat16* __restrict__ sl)
{
    int row = blockIdx.x;
    int tid = threadIdx.x;
    float v = H[(size_t)row * DH + tid];
    __shared__ float red[256];
    red[tid] = v * v;
    __syncthreads();
    for (int s = 128; s > 0; s >>= 1) {
        if (tid < s) red[tid] += red[tid + s];
        __syncthreads();
    }
    float sc = 1.0f / fmaxf(sqrtf(red[0]), 1e-12f);
    float nv = v * sc;
    __nv_bfloat16 h = __float2bfloat16(nv);
    float r = nv - __bfloat162float(h);
    sh[(size_t)row * DH + tid] = h;
    sl[(size_t)row * DH + tid] = __float2bfloat16(r);
}

// ---------------- sinkhorn factor passes ----------------
__global__ void colsum_k(const float* __restrict__ Eb, const float* __restrict__ r,
                         float* __restrict__ cs)
{
    int j = blockIdx.x * 256 + threadIdx.x;
    int i0 = blockIdx.y * 128;
    float acc = 0.f;
    #pragma unroll 4
    for (int i = 0; i < 128; i++)
        acc += Eb[(size_t)(i0 + i) * NMAX + j] * __ldg(&r[i0 + i]);
    atomicAdd(&cs[j], acc);
}

__global__ void rowsum_k(const float* __restrict__ Eb, const float* __restrict__ c,
                         float* __restrict__ r)
{
    int i = blockIdx.x, tid = threadIdx.x;
    const float4* row = reinterpret_cast<const float4*>(Eb + (size_t)i * NMAX);
    const float4* c4 = reinterpret_cast<const float4*>(c);
    float acc = 0.f;
    for (int j = tid; j < NMAX / 4; j += 256) {
        float4 e = row[j], cv = c4[j];
        acc += e.x * cv.x + e.y * cv.y + e.z * cv.z + e.w * cv.w;
    }
    __shared__ float red[256];
    red[tid] = acc;
    __syncthreads();
    for (int s = 128; s > 0; s >>= 1) {
        if (tid < s) red[tid] += red[tid + s];
        __syncthreads();
    }
    if (tid == 0) r[i] = 1.0f / red[0];
}

__global__ void finalize_k(const float* __restrict__ Eb, const float* __restrict__ r,
                           const float* __restrict__ c, float* __restrict__ out, int rows)
{
    int t = blockIdx.x * blockDim.x + threadIdx.x;
    if (t >= rows * (NMAX / 4)) return;
    int i = t >> 10, j = t & 1023;
    float ri = r[i];
    float4 e = reinterpret_cast<const float4*>(Eb)[(size_t)i * (NMAX / 4) + j];
    float4 cv = reinterpret_cast<const float4*>(c)[j];
    float4 o;
    o.x = e.x * ri * cv.x; o.y = e.y * ri * cv.y;
    o.z = e.z * ri * cv.z; o.w = e.w * ri * cv.w;
    reinterpret_cast<float4*>(out)[t] = o;
}

// ---------------- host driver ----------------
static inline int cdiv(int a, int b) { return (a + b - 1) / b; }

extern "C" void kernel_launch(void* const* d_in, const int* in_sizes, int n_in,
                              void* d_out, int out_size)
{
    const float* x_s = (const float*)d_in[0];
    const float* x_t = (const float*)d_in[1];
    const int* edges = (const int*)d_in[2];
    const int* edget = (const int*)d_in[3];
    const float* W1[3], *W2[3], *Wr[3], *br[3];
    for (int l = 0; l < 3; l++) {
        W1[l] = (const float*)d_in[4 + 4 * l];
        W2[l] = (const float*)d_in[5 + 4 * l];
        Wr[l] = (const float*)d_in[6 + 4 * l];
        br[l] = (const float*)d_in[7 + 4 * l];
    }
    const float* final_w = (const float*)d_in[16];
    const float* final_b = (const float*)d_in[17];

    const int NS = in_sizes[0] / 128;
    const int NT = in_sizes[1] / 128;
    const int ES = in_sizes[2] / 2;
    const int ET = in_sizes[3] / 2;

    float *tmp12, *agg1, *agg2, *Hf, *Eb, *rr, *cc, *csum, *inv_a, *inv_b;
    int *cnt_a, *cnt_b, *off_a, *off_b, *cur_a, *cur_b, *lst_a, *lst_b;
    __nv_bfloat16 *Xh, *Xl, *Wth, *Wtl, *sh, *sl;
    cudaGetSymbolAddress((void**)&Xh, g_Xh);
    cudaGetSymbolAddress((void**)&Xl, g_Xl);
    cudaGetSymbolAddress((void**)&Wth, g_Wth);
    cudaGetSymbolAddress((void**)&Wtl, g_Wtl);
    cudaGetSymbolAddress((void**)&tmp12, g_tmp12);
    cudaGetSymbolAddress((void**)&agg1, g_agg1);
    cudaGetSymbolAddress((void**)&agg2, g_agg2);
    cudaGetSymbolAddress((void**)&Hf, g_H);
    cudaGetSymbolAddress((void**)&Eb, g_E);
    cudaGetSymbolAddress((void**)&rr, g_r);
    cudaGetSymbolAddress((void**)&cc, g_c);
    cudaGetSymbolAddress((void**)&csum, g_colsum);
    cudaGetSymbolAddress((void**)&cnt_a, g_cnt_a);
    cudaGetSymbolAddress((void**)&cnt_b, g_cnt_b);
    cudaGetSymbolAddress((void**)&inv_a, g_inv_a);
    cudaGetSymbolAddress((void**)&inv_b, g_inv_b);
    cudaGetSymbolAddress((void**)&off_a, g_off_a);
    cudaGetSymbolAddress((void**)&off_b, g_off_b);
    cudaGetSymbolAddress((void**)&cur_a, g_cur_a);
    cudaGetSymbolAddress((void**)&cur_b, g_cur_b);
    cudaGetSymbolAddress((void**)&lst_a, g_lst_a);
    cudaGetSymbolAddress((void**)&lst_b, g_lst_b);
    cudaGetSymbolAddress((void**)&sh, g_sh);
    cudaGetSymbolAddress((void**)&sl, g_sl);

    // ---- weight layout: per layer [W1;W2] fused [512][K], Wr [256][K], final ----
    int woff12[3], woffr[3], wofff;
    {
        int o = 0, fan = 128;
        for (int l = 0; l < 3; l++) {
            woff12[l] = o; o += 512 * fan;
            woffr[l] = o;  o += 256 * fan;
            fan = DH;
        }
        wofff = o;  // 896*256
    }
    for (int l = 0; l < 3; l++) {
        int fan = (l == 0) ? 128 : DH;
        wtsplit_k<<<cdiv(fan * DH, 256), 256>>>(W1[l], Wth + woff12[l],
                                                Wtl + woff12[l], fan, DH);
        wtsplit_k<<<cdiv(fan * DH, 256), 256>>>(W2[l], Wth + woff12[l] + 256 * fan,
                                                Wtl + woff12[l] + 256 * fan, fan, DH);
        wtsplit_k<<<cdiv(fan * DH, 256), 256>>>(Wr[l], Wth + woffr[l],
                                                Wtl + woffr[l], fan, DH);
    }
    wtsplit_k<<<cdiv(DCAT * DH, 256), 256>>>(final_w, Wth + wofff, Wtl + wofff,
                                             DCAT, DH);

    for (int gi = 0; gi < 2; gi++) {
        const float* x = gi == 0 ? x_s : x_t;
        const int* ep = gi == 0 ? edges : edget;
        int N = gi == 0 ? NS : NT;
        int E = gi == 0 ? ES : ET;
        const int* src = ep;
        const int* dst = ep + E;
        __nv_bfloat16* Xgh = Xh + (size_t)gi * NMAX * DCAT;
        __nv_bfloat16* Xgl = Xl + (size_t)gi * NMAX * DCAT;

        copyx_split<<<cdiv(N * 128, 256), 256>>>(x, Xgh, Xgl, N);

        // ---- CSR build (both directions) ----
        fill_i2<<<cdiv(NMAX, 256), 256>>>(cnt_a, cnt_b, NMAX);
        count2_k<<<cdiv(E, 256), 256>>>(dst, src, cnt_a, cnt_b, E);
        inv2_k<<<cdiv(NMAX, 256), 256>>>(cnt_a, cnt_b, inv_a, inv_b, NMAX);
        scan2_k<<<2, 1024>>>(cnt_a, cnt_b, off_a, off_b, cur_a, cur_b);
        place2_k<<<cdiv(E, 256), 256>>>(dst, src, cur_a, cur_b, lst_a, lst_b, E);

        int off = 0, fan = 128;
        for (int l = 0; l < 3; l++) {
            const __nv_bfloat16* Ahp = Xgh + off;
            const __nv_bfloat16* Alp = Xgl + off;
            // fused W1|W2 GEMM: N=512
            dim3 g12(8, cdiv(N, 64));
            gemm_f<0><<<g12, 128>>>(Ahp, Alp, DCAT,
                                    Wth + woff12[l], Wtl + woff12[l],
                                    tmp12, 512, N, fan, nullptr, nullptr, nullptr,
                                    nullptr, nullptr);
            gather_k<<<N, 256>>>(tmp12, 512, off_a, cnt_a, inv_a, lst_a, agg1);
            gather_k<<<N, 256>>>(tmp12 + 256, 512, off_b, cnt_b, inv_b, lst_b, agg2);
            int noff = off + fan;   // 0->128, 128->384, 384->640
            dim3 gr(4, cdiv(N, 64));
            gemm_f<1><<<gr, 128>>>(Ahp, Alp, DCAT,
                                   Wth + woffr[l], Wtl + woffr[l],
                                   nullptr, DCAT, N, fan, br[l], agg1, agg2,
                                   Xgh + noff, Xgl + noff);
            off = noff;
            fan = DH;
        }
        // final linear: H = Xcat @ final_w + final_b (K = 896)
        dim3 gridf(4, cdiv(N, 64));
        gemm_f<3><<<gridf, 128>>>(Xgh, Xgl, DCAT, Wth + wofff, Wtl + wofff,
                                  Hf, DH, N, DCAT, final_b, nullptr, nullptr,
                                  nullptr, nullptr);
        l2split_k<<<N, 256>>>(Hf, sh + (size_t)gi * NMAX * DH,
                              sl + (size_t)gi * NMAX * DH);
    }

    // match -> E = exp(20*(Hs_n @ Ht_n^T + 1e-10)) via mma.sync bf16 split-2
    {
        dim3 gm(NMAX / 128, NMAX / 128);
        match_mma_kernel<<<gm, 256>>>(sh, sl,
                                      sh + (size_t)NMAX * DH, sl + (size_t)NMAX * DH, Eb);
        // dummy rows: exp(20*(eps+eps)) == 1.0f in fp32
        fill_f<<<cdiv((NMAX - NS) * NMAX, 256), 256>>>(Eb + (size_t)NS * NMAX, 1.0f,
                                                       (NMAX - NS) * NMAX);
    }

    // sinkhorn via row/col scale factors: 5x (col-norm, row-norm)
    fill_f<<<cdiv(NMAX, 256), 256>>>(rr, 1.0f, NMAX);
    for (int it = 0; it < 5; it++) {
        fill_f<<<cdiv(NMAX, 256), 256>>>(csum, 0.f, NMAX);
        colsum_k<<<dim3(NMAX / 256, 32), 256>>>(Eb, rr, csum);
        recip_k<<<cdiv(NMAX, 256), 256>>>(csum, cc, NMAX);
        rowsum_k<<<NMAX, 256>>>(Eb, cc, rr);
    }
    finalize_k<<<cdiv(NS * (NMAX / 4), 256), 256>>>(Eb, rr, cc, (float*)d_out, NS);
}

// round 7
// speedup vs baseline: 2.4288x; 1.1630x over previous
#include <cuda_runtime.h>
#include <cuda_bf16.h>
#include <math.h>
#include <stdint.h>

#define NMAX 4096
#define NTOT 8192            // both graphs stacked
#define DH   256
#define DCAT 896
#define EMAX 65536
#define WTOT 720896

// ---------------- scratch (device globals; no runtime alloc) ----------------
__device__ __align__(16) __nv_bfloat16 g_Xh[(size_t)NTOT * DCAT];
__device__ __align__(16) __nv_bfloat16 g_Xl[(size_t)NTOT * DCAT];
__device__ __align__(16) __nv_bfloat16 g_Wth[WTOT];
__device__ __align__(16) __nv_bfloat16 g_Wtl[WTOT];
__device__ __align__(16) float g_tmp12[(size_t)NTOT * 512];
__device__ __align__(16) float g_agg1[(size_t)NTOT * DH];
__device__ __align__(16) float g_agg2[(size_t)NTOT * DH];
__device__ __align__(16) float g_H[(size_t)NTOT * DH];
__device__ __align__(16) float g_E[(size_t)NMAX * NMAX];   // 64MB
__device__ __align__(16) float g_r[NMAX];
__device__ __align__(16) float g_csum[5 * NMAX];
__device__ __align__(16) int   g_cnt_a[NTOT];
__device__ __align__(16) int   g_cnt_b[NTOT];
__device__ __align__(16) float g_inv_a[NTOT];
__device__ __align__(16) float g_inv_b[NTOT];
__device__ __align__(16) int g_off_a[NTOT];
__device__ __align__(16) int g_off_b[NTOT];
__device__ __align__(16) int g_cur_a[NTOT];
__device__ __align__(16) int g_cur_b[NTOT];
__device__ __align__(16) int g_lst_a[2 * EMAX];
__device__ __align__(16) int g_lst_b[2 * EMAX];
__device__ __align__(16) __nv_bfloat16 g_sh[(size_t)NTOT * DH];
__device__ __align__(16) __nv_bfloat16 g_sl[(size_t)NTOT * DH];

// ---------------- PTX helpers ----------------
__device__ __forceinline__ uint32_t smem_u32(const void* p) {
    uint32_t a;
    asm("{ .reg .u64 t; cvta.to.shared.u64 t, %1; cvt.u32.u64 %0, t; }" : "=r"(a) : "l"(p));
    return a;
}
#define CP_ASYNC16(saddr, gptr) \
    asm volatile("cp.async.cg.shared.global [%0], [%1], 16;" :: "r"(saddr), "l"(gptr))
#define CP_COMMIT() asm volatile("cp.async.commit_group;" ::: "memory")
#define CP_WAIT1()  asm volatile("cp.async.wait_group 1;" ::: "memory")

__device__ __forceinline__ void ldm_x4(uint32_t* r, uint32_t addr) {
    asm volatile("ldmatrix.sync.aligned.m8n8.x4.shared.b16 {%0,%1,%2,%3}, [%4];"
        : "=r"(r[0]), "=r"(r[1]), "=r"(r[2]), "=r"(r[3]) : "r"(addr));
}
__device__ __forceinline__ void mma_bf16(float* d, const uint32_t* a, uint32_t b0, uint32_t b1) {
    asm volatile(
        "mma.sync.aligned.m16n8k16.row.col.f32.bf16.bf16.f32 "
        "{%0,%1,%2,%3}, {%4,%5,%6,%7}, {%8,%9}, {%0,%1,%2,%3};"
        : "+f"(d[0]), "+f"(d[1]), "+f"(d[2]), "+f"(d[3])
        : "r"(a[0]), "r"(a[1]), "r"(a[2]), "r"(a[3]), "r"(b0), "r"(b1));
}

// ---------------- utility kernels ----------------
__global__ void fill_f(float* p, float v, int n) {
    int t = blockIdx.x * blockDim.x + threadIdx.x;
    if (t < n) p[t] = v;
}
__global__ void fill_i2(int* a, int* b, int n) {
    int t = blockIdx.x * blockDim.x + threadIdx.x;
    if (t < n) { a[t] = 0; b[t] = 0; }
}
__global__ void count_both(const int* __restrict__ d0, const int* __restrict__ s0, int E0,
                           const int* __restrict__ d1, const int* __restrict__ s1, int E1,
                           int* __restrict__ ca, int* __restrict__ cb)
{
    int t = blockIdx.x * blockDim.x + threadIdx.x;
    if (t < E0) {
        atomicAdd(&ca[d0[t]], 1); atomicAdd(&cb[s0[t]], 1);
    } else if (t < E0 + E1) {
        int u = t - E0;
        atomicAdd(&ca[NMAX + d1[u]], 1); atomicAdd(&cb[NMAX + s1[u]], 1);
    }
}
__global__ void inv_both(const int* __restrict__ ca, const int* __restrict__ cb,
                         float* __restrict__ ia, float* __restrict__ ib)
{
    int t = blockIdx.x * blockDim.x + threadIdx.x;
    if (t < NTOT) {
        ia[t] = 1.0f / (float)max(ca[t], 1);
        ib[t] = 1.0f / (float)max(cb[t], 1);
    }
}
// 4 blocks: (dir,gi). exclusive scan of NMAX counts + base offset
__global__ void scan4_k(const int* __restrict__ ca, const int* __restrict__ cb,
                        int* __restrict__ oa, int* __restrict__ ob,
                        int* __restrict__ ra, int* __restrict__ rb, int E0)
{
    __shared__ int s[NMAX];
    int b = blockIdx.x;
    int gi = b & 1, dir = b >> 1;
    const int* cnt = (dir ? cb : ca) + gi * NMAX;
    int* off = (dir ? ob : oa) + gi * NMAX;
    int* cur = (dir ? rb : ra) + gi * NMAX;
    int base = gi ? E0 : 0;
    int tid = threadIdx.x;
    #pragma unroll
    for (int j = 0; j < 4; j++) s[tid + j * 1024] = cnt[tid + j * 1024];
    __syncthreads();
    for (int d = 1; d < NMAX; d <<= 1) {
        int v[4];
        #pragma unroll
        for (int j = 0; j < 4; j++) {
            int i = tid + j * 1024;
            v[j] = (i >= d) ? s[i - d] : 0;
        }
        __syncthreads();
        #pragma unroll
        for (int j = 0; j < 4; j++) s[tid + j * 1024] += v[j];
        __syncthreads();
    }
    #pragma unroll
    for (int j = 0; j < 4; j++) {
        int i = tid + j * 1024;
        int o = base + s[i] - cnt[i];
        off[i] = o;
        cur[i] = o;
    }
}
__global__ void place_both(const int* __restrict__ d0, const int* __restrict__ s0, int E0,
                           const int* __restrict__ d1, const int* __restrict__ s1, int E1,
                           int* __restrict__ ca, int* __restrict__ cb,
                           int* __restrict__ la, int* __restrict__ lb)
{
    int t = blockIdx.x * blockDim.x + threadIdx.x;
    if (t < E0) {
        int d = d0[t], s = s0[t];
        la[atomicAdd(&ca[d], 1)] = s;
        lb[atomicAdd(&cb[s], 1)] = d;
    } else if (t < E0 + E1) {
        int u = t - E0;
        int d = d1[u], s = s1[u];
        la[atomicAdd(&ca[NMAX + d], 1)] = NMAX + s;
        lb[atomicAdd(&cb[NMAX + s], 1)] = NMAX + d;
    }
}

// CSR gather-mean, float4 per thread (64 threads cover 256 cols)
__global__ void __launch_bounds__(64) gather_k(
    const float* __restrict__ vals, int ldv, const int* __restrict__ off,
    const int* __restrict__ cnt, const float* __restrict__ inv,
    const int* __restrict__ lst, float* __restrict__ out)
{
    __shared__ int sl[64];
    const int n = blockIdx.x;
    const int tid = threadIdx.x;          // 0..63
    const int beg = off[n];
    const int d = cnt[n];
    const int c4 = tid * 4;
    float4 acc = make_float4(0.f, 0.f, 0.f, 0.f);
    for (int base = 0; base < d; base += 64) {
        int chunk = min(64, d - base);
        if (tid < chunk) sl[tid] = lst[beg + base + tid];
        __syncthreads();
        int e = 0;
        for (; e + 4 <= chunk; e += 4) {
            float4 v0 = *reinterpret_cast<const float4*>(vals + (size_t)sl[e] * ldv + c4);
            float4 v1 = *reinterpret_cast<const float4*>(vals + (size_t)sl[e + 1] * ldv + c4);
            float4 v2 = *reinterpret_cast<const float4*>(vals + (size_t)sl[e + 2] * ldv + c4);
            float4 v3 = *reinterpret_cast<const float4*>(vals + (size_t)sl[e + 3] * ldv + c4);
            acc.x += (v0.x + v1.x) + (v2.x + v3.x);
            acc.y += (v0.y + v1.y) + (v2.y + v3.y);
            acc.z += (v0.z + v1.z) + (v2.z + v3.z);
            acc.w += (v0.w + v1.w) + (v2.w + v3.w);
        }
        for (; e < chunk; e++) {
            float4 v = *reinterpret_cast<const float4*>(vals + (size_t)sl[e] * ldv + c4);
            acc.x += v.x; acc.y += v.y; acc.z += v.z; acc.w += v.w;
        }
        __syncthreads();
    }
    float iv = inv[n];
    acc.x *= iv; acc.y *= iv; acc.z *= iv; acc.w *= iv;
    *reinterpret_cast<float4*>(out + (size_t)n * DH + c4) = acc;
}

// both graphs' input features -> bf16 hi/lo into X cols 0..127
__global__ void copyx_both(const float* __restrict__ xs, int NS,
                           const float* __restrict__ xt, int NT,
                           __nv_bfloat16* __restrict__ Xh, __nv_bfloat16* __restrict__ Xl)
{
    int t = blockIdx.x * blockDim.x + threadIdx.x;
    int n0 = NS * 128;
    float v;
    size_t dsti;
    if (t < n0) {
        v = xs[t];
        dsti = (size_t)(t >> 7) * DCAT + (t & 127);
    } else if (t < n0 + NT * 128) {
        int u = t - n0;
        v = xt[u];
        dsti = (size_t)(NMAX + (u >> 7)) * DCAT + (u & 127);
    } else return;
    __nv_bfloat16 h = __float2bfloat16(v);
    Xh[dsti] = h;
    Xl[dsti] = __float2bfloat16(v - __bfloat162float(h));
}

// all weights transpose+split in one kernel
struct WPack {
    const float* src[10];
    int dstoff[10];
    int K[10];
    int start[11];
};
__global__ void wtsplit_all(WPack wp, __nv_bfloat16* __restrict__ th,
                            __nv_bfloat16* __restrict__ tl)
{
    int t = blockIdx.x * blockDim.x + threadIdx.x;
    if (t >= WTOT) return;
    int seg = 0;
    #pragma unroll
    for (int i = 1; i < 10; i++) seg += (t >= wp.start[i]);
    int u = t - wp.start[seg];
    int K = wp.K[seg];
    int k = u >> 8, n = u & 255;          // all N == 256
    float v = wp.src[seg][u];
    __nv_bfloat16 h = __float2bfloat16(v);
    size_t di = (size_t)wp.dstoff[seg] + (size_t)n * K + k;
    th[di] = h;
    tl[di] = __float2bfloat16(v - __bfloat162float(h));
}

// ---------------- fused GNN GEMM (single k-loop, cp.async 2-stage) ----------
#define GSP 40

template <int EPI>
__global__ void __launch_bounds__(128) gemm_f(
    const __nv_bfloat16* __restrict__ Ah, const __nv_bfloat16* __restrict__ Al, int lda,
    const __nv_bfloat16* __restrict__ Bh, const __nv_bfloat16* __restrict__ Bl,
    float* __restrict__ C, int ldc, int M, int K,
    const float* __restrict__ bias, const float* __restrict__ add1,
    const float* __restrict__ add2,
    __nv_bfloat16* __restrict__ Oh, __nv_bfloat16* __restrict__ Ol)
{
    __shared__ __nv_bfloat16 s[2][4][64 * GSP];
    const int tid = threadIdx.x;
    const int lane = tid & 31, wid = tid >> 5;
    const int wm = wid & 1, wn = wid >> 1;
    const int row0 = blockIdx.y * 64, col0 = blockIdx.x * 64;
    const int nk = K / 32;

    const __nv_bfloat16* base[4] = {
        Ah + (size_t)row0 * lda, Al + (size_t)row0 * lda,
        Bh + (size_t)col0 * K, Bl + (size_t)col0 * K };
    const int ld4[4] = { lda, lda, K, K };

    const int l_row = tid >> 1;
    const int l_q0 = (tid & 1) * 2;

    auto load_stage = [&](int kc, int st) {
        #pragma unroll
        for (int t4 = 0; t4 < 4; t4++) {
            const __nv_bfloat16* g = base[t4] + (size_t)l_row * ld4[t4] + kc * 32;
            uint32_t sa = smem_u32(&s[st][t4][l_row * GSP]);
            CP_ASYNC16(sa + (l_q0 + 0) * 16, g + (l_q0 + 0) * 8);
            CP_ASYNC16(sa + (l_q0 + 1) * 16, g + (l_q0 + 1) * 8);
        }
    };

    float acc[2][4][4];
    #pragma unroll
    for (int i = 0; i < 2; i++)
        #pragma unroll
        for (int j = 0; j < 4; j++)
            #pragma unroll
            for (int q = 0; q < 4; q++) acc[i][j][q] = 0.f;

    const int a_row = wm * 32 + (lane < 16 ? lane : lane - 16);
    const int a_col = (lane < 16 ? 0 : 8);
    const int b_row = wn * 32 + (lane & 7);
    const int b_col = (lane >> 3) * 8;

    load_stage(0, 0);
    CP_COMMIT();

    for (int kc = 0; kc < nk; kc++) {
        if (kc + 1 < nk) load_stage(kc + 1, (kc + 1) & 1);
        CP_COMMIT();
        CP_WAIT1();
        __syncthreads();
        const int st = kc & 1;

        uint32_t bh[4][4], bl[4][4];
        #pragma unroll
        for (int j = 0; j < 4; j++) {
            ldm_x4(bh[j], smem_u32(&s[st][2][(b_row + j * 8) * GSP + b_col]));
            ldm_x4(bl[j], smem_u32(&s[st][3][(b_row + j * 8) * GSP + b_col]));
        }
        #pragma unroll
        for (int h = 0; h < 2; h++) {
            #pragma unroll
            for (int i = 0; i < 2; i++) {
                uint32_t ah[4], al[4];
                ldm_x4(ah, smem_u32(&s[st][0][(a_row + i * 16) * GSP + h * 16 + a_col]));
                ldm_x4(al, smem_u32(&s[st][1][(a_row + i * 16) * GSP + h * 16 + a_col]));
                #pragma unroll
                for (int j = 0; j < 4; j++) {
                    mma_bf16(acc[i][j], ah, bh[j][2 * h], bh[j][2 * h + 1]);
                    mma_bf16(acc[i][j], ah, bl[j][2 * h], bl[j][2 * h + 1]);
                    mma_bf16(acc[i][j], al, bh[j][2 * h], bh[j][2 * h + 1]);
                }
            }
        }
        __syncthreads();
    }

    const int er = lane >> 2, ec = (lane & 3) * 2;
    #pragma unroll
    for (int i = 0; i < 2; i++) {
        #pragma unroll
        for (int j = 0; j < 4; j++) {
            int gc = col0 + wn * 32 + j * 8 + ec;
            #pragma unroll
            for (int rr = 0; rr < 2; rr++) {
                int row = row0 + wm * 32 + i * 16 + er + rr * 8;
                if (row >= M) continue;
                float v0 = acc[i][j][2 * rr + 0];
                float v1 = acc[i][j][2 * rr + 1];
                if (EPI == 0) {
                    *reinterpret_cast<float2*>(C + (size_t)row * ldc + gc) =
                        make_float2(v0, v1);
                } else if (EPI == 1) {
                    v0 = fmaxf(v0 + bias[gc] + add1[(size_t)row * DH + gc]
                                  + add2[(size_t)row * DH + gc], 0.f);
                    v1 = fmaxf(v1 + bias[gc + 1] + add1[(size_t)row * DH + gc + 1]
                                  + add2[(size_t)row * DH + gc + 1], 0.f);
                    __nv_bfloat16 h0 = __float2bfloat16(v0);
                    __nv_bfloat16 h1 = __float2bfloat16(v1);
                    __nv_bfloat16 l0 = __float2bfloat16(v0 - __bfloat162float(h0));
                    __nv_bfloat16 l1 = __float2bfloat16(v1 - __bfloat162float(h1));
                    __nv_bfloat162 hv; hv.x = h0; hv.y = h1;
                    __nv_bfloat162 lv; lv.x = l0; lv.y = l1;
                    *reinterpret_cast<__nv_bfloat162*>(Oh + (size_t)row * ldc + gc) = hv;
                    *reinterpret_cast<__nv_bfloat162*>(Ol + (size_t)row * ldc + gc) = lv;
                } else {  // EPI == 3
                    *reinterpret_cast<float2*>(C + (size_t)row * ldc + gc) =
                        make_float2(v0 + bias[gc], v1 + bias[gc + 1]);
                }
            }
        }
    }
}

// ---------------- match GEMM (3-pass, cp.async 2-stage) ----------------
#define SPAD 40

__global__ void __launch_bounds__(256, 2) match_mma_kernel(
    const __nv_bfloat16* __restrict__ Ah, const __nv_bfloat16* __restrict__ Al,
    const __nv_bfloat16* __restrict__ Bh, const __nv_bfloat16* __restrict__ Bl,
    float* __restrict__ Eout)
{
    __shared__ __nv_bfloat16 s[2][2][128 * SPAD];
    const int tid = threadIdx.x;
    const int wid = tid >> 5, lane = tid & 31;
    const int wm = wid & 3, wn = wid >> 2;
    const int row0 = blockIdx.y * 128, col0 = blockIdx.x * 128;

    const __nv_bfloat16* Asrc[3] = {
        Ah + (size_t)row0 * DH, Ah + (size_t)row0 * DH, Al + (size_t)row0 * DH };
    const __nv_bfloat16* Bsrc[3] = {
        Bh + (size_t)col0 * DH, Bl + (size_t)col0 * DH, Bh + (size_t)col0 * DH };

    const int l_row = tid >> 1;
    const int l_q0 = (tid & 1) * 2;

    auto load_stage = [&](int it, int st) {
        int p = it >> 3, kc = it & 7;
        const __nv_bfloat16* ga = Asrc[p] + (size_t)l_row * DH + kc * 32;
        const __nv_bfloat16* gb = Bsrc[p] + (size_t)l_row * DH + kc * 32;
        uint32_t sa = smem_u32(&s[st][0][l_row * SPAD]);
        uint32_t sb = smem_u32(&s[st][1][l_row * SPAD]);
        CP_ASYNC16(sa + (l_q0 + 0) * 16, ga + (l_q0 + 0) * 8);
        CP_ASYNC16(sa + (l_q0 + 1) * 16, ga + (l_q0 + 1) * 8);
        CP_ASYNC16(sb + (l_q0 + 0) * 16, gb + (l_q0 + 0) * 8);
        CP_ASYNC16(sb + (l_q0 + 1) * 16, gb + (l_q0 + 1) * 8);
    };

    float acc[2][8][4];
    #pragma unroll
    for (int i = 0; i < 2; i++)
        #pragma unroll
        for (int j = 0; j < 8; j++)
            #pragma unroll
            for (int q = 0; q < 4; q++) acc[i][j][q] = 0.f;

    const int a_row = wm * 32 + (lane < 16 ? lane : lane - 16);
    const int a_col = (lane < 16 ? 0 : 8);
    const int b_row = wn * 64 + (lane & 7);
    const int b_col = (lane >> 3) * 8;

    load_stage(0, 0);
    CP_COMMIT();

    for (int it = 0; it < 24; it++) {
        if (it + 1 < 24) load_stage(it + 1, (it + 1) & 1);
        CP_COMMIT();
        CP_WAIT1();
        __syncthreads();
        const int st = it & 1;

        uint32_t bfr[8][4];
        #pragma unroll
        for (int j = 0; j < 8; j++)
            ldm_x4(bfr[j], smem_u32(&s[st][1][(b_row + j * 8) * SPAD + b_col]));

        #pragma unroll
        for (int h = 0; h < 2; h++) {
            #pragma unroll
            for (int i = 0; i < 2; i++) {
                uint32_t afr[4];
                ldm_x4(afr, smem_u32(&s[st][0][(a_row + i * 16) * SPAD + h * 16 + a_col]));
                #pragma unroll
                for (int j = 0; j < 8; j++)
                    mma_bf16(acc[i][j], afr, bfr[j][2 * h], bfr[j][2 * h + 1]);
            }
        }
        __syncthreads();
    }

    const int er = lane >> 2, ec = (lane & 3) * 2;
    #pragma unroll
    for (int i = 0; i < 2; i++) {
        int gr0 = row0 + wm * 32 + i * 16 + er;
        #pragma unroll
        for (int j = 0; j < 8; j++) {
            int gc = col0 + wn * 64 + j * 8 + ec;
            float2 o0, o1;
            o0.x = __expf(20.f * (acc[i][j][0] + 1e-10f));
            o0.y = __expf(20.f * (acc[i][j][1] + 1e-10f));
            o1.x = __expf(20.f * (acc[i][j][2] + 1e-10f));
            o1.y = __expf(20.f * (acc[i][j][3] + 1e-10f));
            *reinterpret_cast<float2*>(Eout + (size_t)gr0 * NMAX + gc) = o0;
            *reinterpret_cast<float2*>(Eout + (size_t)(gr0 + 8) * NMAX + gc) = o1;
        }
    }
}

// ---------------- fused L2 normalize + bf16 split (zero dummy rows) --------
__global__ void l2split_k(const float* __restrict__ H, __nv_bfloat16* __restrict__ sh,
                          __nv_bfloat16* __restrict__ sl, int NS)
{
    int row = blockIdx.x;
    int tid = threadIdx.x;
    if (row >= NS && row < NMAX) {
        sh[(size_t)row * DH + tid] = __float2bfloat16(0.f);
        sl[(size_t)row * DH + tid] = __float2bfloat16(0.f);
        return;
    }
    float v = H[(size_t)row * DH + tid];
    __shared__ float red[256];
    red[tid] = v * v;
    __syncthreads();
    for (int s = 128; s > 0; s >>= 1) {
        if (tid < s) red[tid] += red[tid + s];
        __syncthreads();
    }
    float sc = 1.0f / fmaxf(sqrtf(red[0]), 1e-12f);
    float nv = v * sc;
    __nv_bfloat16 h = __float2bfloat16(nv);
    sh[(size_t)row * DH + tid] = h;
    sl[(size_t)row * DH + tid] = __float2bfloat16(nv - __bfloat162float(h));
}

// ---------------- sinkhorn ----------------
template <bool HASR>
__global__ void colsum_k(const float* __restrict__ Eb, const float* __restrict__ r,
                         float* __restrict__ cs)
{
    int j = blockIdx.x * 256 + threadIdx.x;
    int i0 = blockIdx.y * 128;
    float acc = 0.f;
    #pragma unroll 4
    for (int i = 0; i < 128; i++) {
        float e = Eb[(size_t)(i0 + i) * NMAX + j];
        acc += HASR ? e * __ldg(&r[i0 + i]) : e;
    }
    atomicAdd(&cs[j], acc);
}

// r[i] = 1/sum_j E[i][j] * (1/csum[j])
__global__ void rowsum_k(const float* __restrict__ Eb, const float* __restrict__ csum,
                         float* __restrict__ r)
{
    __shared__ float sc[NMAX];
    __shared__ float red[256];
    int i = blockIdx.x, tid = threadIdx.x;
    for (int j = tid; j < NMAX; j += 256) sc[j] = 1.0f / csum[j];
    __syncthreads();
    const float4* row = reinterpret_cast<const float4*>(Eb + (size_t)i * NMAX);
    const float4* c4 = reinterpret_cast<const float4*>(sc);
    float acc = 0.f;
    for (int j = tid; j < NMAX / 4; j += 256) {
        float4 e = row[j], cv = c4[j];
        acc += e.x * cv.x + e.y * cv.y + e.z * cv.z + e.w * cv.w;
    }
    red[tid] = acc;
    __syncthreads();
    for (int s = 128; s > 0; s >>= 1) {
        if (tid < s) red[tid] += red[tid + s];
        __syncthreads();
    }
    if (tid == 0) r[i] = 1.0f / red[0];
}

// out[i][j] = E[i][j]*r[i]/csum_last[j]
__global__ void finalize_k(const float* __restrict__ Eb, const float* __restrict__ r,
                           const float* __restrict__ csum, float* __restrict__ out, int rows)
{
    int t = blockIdx.x * blockDim.x + threadIdx.x;
    if (t >= rows * (NMAX / 4)) return;
    int i = t >> 10, j = t & 1023;
    float ri = r[i];
    float4 e = reinterpret_cast<const float4*>(Eb)[(size_t)i * (NMAX / 4) + j];
    float4 cs = reinterpret_cast<const float4*>(csum)[j];
    float4 o;
    o.x = e.x * ri / cs.x; o.y = e.y * ri / cs.y;
    o.z = e.z * ri / cs.z; o.w = e.w * ri / cs.w;
    reinterpret_cast<float4*>(out)[t] = o;
}

// ---------------- host driver ----------------
static inline int cdiv(int a, int b) { return (a + b - 1) / b; }

extern "C" void kernel_launch(void* const* d_in, const int* in_sizes, int n_in,
                              void* d_out, int out_size)
{
    const float* x_s = (const float*)d_in[0];
    const float* x_t = (const float*)d_in[1];
    const int* edges = (const int*)d_in[2];
    const int* edget = (const int*)d_in[3];
    const float* W1[3], *W2[3], *Wr[3], *br[3];
    for (int l = 0; l < 3; l++) {
        W1[l] = (const float*)d_in[4 + 4 * l];
        W2[l] = (const float*)d_in[5 + 4 * l];
        Wr[l] = (const float*)d_in[6 + 4 * l];
        br[l] = (const float*)d_in[7 + 4 * l];
    }
    const float* final_w = (const float*)d_in[16];
    const float* final_b = (const float*)d_in[17];

    const int NS = in_sizes[0] / 128;
    const int NT = in_sizes[1] / 128;
    const int ES = in_sizes[2] / 2;
    const int ET = in_sizes[3] / 2;

    float *tmp12, *agg1, *agg2, *Hf, *Eb, *rr, *csum, *inv_a, *inv_b;
    int *cnt_a, *cnt_b, *off_a, *off_b, *cur_a, *cur_b, *lst_a, *lst_b;
    __nv_bfloat16 *Xh, *Xl, *Wth, *Wtl, *sh, *sl;
    cudaGetSymbolAddress((void**)&Xh, g_Xh);
    cudaGetSymbolAddress((void**)&Xl, g_Xl);
    cudaGetSymbolAddress((void**)&Wth, g_Wth);
    cudaGetSymbolAddress((void**)&Wtl, g_Wtl);
    cudaGetSymbolAddress((void**)&tmp12, g_tmp12);
    cudaGetSymbolAddress((void**)&agg1, g_agg1);
    cudaGetSymbolAddress((void**)&agg2, g_agg2);
    cudaGetSymbolAddress((void**)&Hf, g_H);
    cudaGetSymbolAddress((void**)&Eb, g_E);
    cudaGetSymbolAddress((void**)&rr, g_r);
    cudaGetSymbolAddress((void**)&csum, g_csum);
    cudaGetSymbolAddress((void**)&cnt_a, g_cnt_a);
    cudaGetSymbolAddress((void**)&cnt_b, g_cnt_b);
    cudaGetSymbolAddress((void**)&inv_a, g_inv_a);
    cudaGetSymbolAddress((void**)&inv_b, g_inv_b);
    cudaGetSymbolAddress((void**)&off_a, g_off_a);
    cudaGetSymbolAddress((void**)&off_b, g_off_b);
    cudaGetSymbolAddress((void**)&cur_a, g_cur_a);
    cudaGetSymbolAddress((void**)&cur_b, g_cur_b);
    cudaGetSymbolAddress((void**)&lst_a, g_lst_a);
    cudaGetSymbolAddress((void**)&lst_b, g_lst_b);
    cudaGetSymbolAddress((void**)&sh, g_sh);
    cudaGetSymbolAddress((void**)&sl, g_sl);

    // weight layout: per layer [W1;W2] fused [512][K], Wr [256][K], final [256][896]
    int woff12[3], woffr[3], wofff;
    {
        int o = 0, fan = 128;
        for (int l = 0; l < 3; l++) {
            woff12[l] = o; o += 512 * fan;
            woffr[l] = o;  o += 256 * fan;
            fan = DH;
        }
        wofff = o;
    }
    {
        WPack wp;
        int s = 0, fan = 128;
        int idx = 0;
        for (int l = 0; l < 3; l++) {
            wp.src[idx] = W1[l]; wp.dstoff[idx] = woff12[l];              wp.K[idx] = fan; wp.start[idx] = s; s += fan * 256; idx++;
            wp.src[idx] = W2[l]; wp.dstoff[idx] = woff12[l] + 256 * fan;  wp.K[idx] = fan; wp.start[idx] = s; s += fan * 256; idx++;
            wp.src[idx] = Wr[l]; wp.dstoff[idx] = woffr[l];               wp.K[idx] = fan; wp.start[idx] = s; s += fan * 256; idx++;
            fan = DH;
        }
        wp.src[idx] = final_w; wp.dstoff[idx] = wofff; wp.K[idx] = DCAT;
        wp.start[idx] = s; s += DCAT * 256;
        wp.start[10] = s;   // == WTOT
        wtsplit_all<<<cdiv(WTOT, 256), 256>>>(wp, Wth, Wtl);
    }

    // input split (both graphs)
    copyx_both<<<cdiv((NS + NT) * 128, 256), 256>>>(x_s, NS, x_t, NT, Xh, Xl);

    // CSR build (both graphs, both directions)
    const int* s0 = edges, *d0 = edges + ES;
    const int* s1 = edget, *d1 = edget + ET;
    fill_i2<<<cdiv(NTOT, 256), 256>>>(cnt_a, cnt_b, NTOT);
    count_both<<<cdiv(ES + ET, 256), 256>>>(d0, s0, ES, d1, s1, ET, cnt_a, cnt_b);
    inv_both<<<cdiv(NTOT, 256), 256>>>(cnt_a, cnt_b, inv_a, inv_b);
    scan4_k<<<4, 1024>>>(cnt_a, cnt_b, off_a, off_b, cur_a, cur_b, ES);
    place_both<<<cdiv(ES + ET, 256), 256>>>(d0, s0, ES, d1, s1, ET,
                                            cur_a, cur_b, lst_a, lst_b);

    // GNN layers (both graphs batched, M = NTOT)
    int off = 0, fan = 128;
    for (int l = 0; l < 3; l++) {
        const __nv_bfloat16* Ahp = Xh + off;
        const __nv_bfloat16* Alp = Xl + off;
        dim3 g12(8, NTOT / 64);
        gemm_f<0><<<g12, 128>>>(Ahp, Alp, DCAT, Wth + woff12[l], Wtl + woff12[l],
                                tmp12, 512, NTOT, fan, nullptr, nullptr, nullptr,
                                nullptr, nullptr);
        gather_k<<<NTOT, 64>>>(tmp12, 512, off_a, cnt_a, inv_a, lst_a, agg1);
        gather_k<<<NTOT, 64>>>(tmp12 + 256, 512, off_b, cnt_b, inv_b, lst_b, agg2);
        int noff = off + fan;
        dim3 gr(4, NTOT / 64);
        gemm_f<1><<<gr, 128>>>(Ahp, Alp, DCAT, Wth + woffr[l], Wtl + woffr[l],
                               nullptr, DCAT, NTOT, fan, br[l], agg1, agg2,
                               Xh + noff, Xl + noff);
        off = noff;
        fan = DH;
    }
    // final linear (K = 896)
    dim3 gridf(4, NTOT / 64);
    gemm_f<3><<<gridf, 128>>>(Xh, Xl, DCAT, Wth + wofff, Wtl + wofff,
                              Hf, DH, NTOT, DCAT, final_b, nullptr, nullptr,
                              nullptr, nullptr);
    l2split_k<<<NTOT, 256>>>(Hf, sh, sl, NS);

    // match GEMM: dummy rows (sh=0) give __expf(2e-9) == 1.0f, matching reference pad
    {
        dim3 gm(NMAX / 128, NMAX / 128);
        match_mma_kernel<<<gm, 256>>>(sh, sl, sh + (size_t)NMAX * DH,
                                      sl + (size_t)NMAX * DH, Eb);
    }

    // sinkhorn: 5x (col-norm, row-norm) via factor tracking
    fill_f<<<cdiv(5 * NMAX, 256), 256>>>(csum, 0.f, 5 * NMAX);
    for (int it = 0; it < 5; it++) {
        float* cs = csum + it * NMAX;
        if (it == 0)
            colsum_k<false><<<dim3(NMAX / 256, 32), 256>>>(Eb, nullptr, cs);
        else
            colsum_k<true><<<dim3(NMAX / 256, 32), 256>>>(Eb, rr, cs);
        rowsum_k<<<NMAX, 256>>>(Eb, cs, rr);
    }
    finalize_k<<<cdiv(NS * (NMAX / 4), 256), 256>>>(Eb, rr, csum + 4 * NMAX,
                                                    (float*)d_out, NS);
}